// round 4
// baseline (speedup 1.0000x reference)
#include <cuda_runtime.h>
#include <math.h>

// Problem constants
#define C_DIM   1024
#define HEADS   16
#define HD      64
#define BATCH   2
#define SEQ     2048
#define M_ROWS  (BATCH*SEQ)        // 4096

// Scratch (device globals: no allocation allowed)
__device__ float g_qkv[(size_t)M_ROWS * 3 * C_DIM];          // [4096, 3072]
__device__ float g_Q[(size_t)BATCH*HEADS*SEQ*HD];            // [B,H,N,D]
__device__ float g_K[(size_t)BATCH*HEADS*SEQ*HD];
__device__ float g_V[(size_t)BATCH*HEADS*SEQ*HD];
__device__ float g_attn[(size_t)M_ROWS * C_DIM];             // [B,N,H*D]
__device__ float g_cos[SEQ * 32];
__device__ float g_sin[SEQ * 32];

// ---------------------------------------------------------------------------
// tf32 / ldmatrix helpers
// ---------------------------------------------------------------------------
__device__ __forceinline__ unsigned f2tf(float x) {
    unsigned r;
    asm("cvt.rna.tf32.f32 %0, %1;" : "=r"(r) : "f"(x));
    return r;
}

__device__ __forceinline__ void mma_tf32(float* d, const unsigned* a, const unsigned* b) {
    asm volatile(
        "mma.sync.aligned.m16n8k8.row.col.f32.tf32.tf32.f32 "
        "{%0,%1,%2,%3}, {%4,%5,%6,%7}, {%8,%9}, {%0,%1,%2,%3};\n"
        : "+f"(d[0]), "+f"(d[1]), "+f"(d[2]), "+f"(d[3])
        : "r"(a[0]), "r"(a[1]), "r"(a[2]), "r"(a[3]), "r"(b[0]), "r"(b[1]));
}

// ldmatrix x4: lane L supplies address for matrix L/8, row L%8 (16B rows).
// Result: reg m of lane(lg,lt) = b32 element [row=lg][col=lt] of matrix m.
__device__ __forceinline__ void ldsm4(unsigned* r, unsigned addr) {
    asm volatile(
        "ldmatrix.sync.aligned.m8n8.x4.shared.b16 {%0,%1,%2,%3}, [%4];"
        : "=r"(r[0]), "=r"(r[1]), "=r"(r[2]), "=r"(r[3]) : "r"(addr));
}

// ---------------------------------------------------------------------------
// tf32 GEMM (NT): C[M,N] = A[M,K] * B[N,K]^T (+ bias)
// Block 128x128, BK=32, 256 threads (8 warps: 2m x 4n, warp tile 64x32)
// Fragments gathered with ldmatrix.x4.
// ---------------------------------------------------------------------------
#define GBM 128
#define GBN 128
#define GBK 32
#define GPAD 4
#define GST  (GBK + GPAD)    // 36 words -> 144B rows: 16B aligned, conflict-free

__global__ __launch_bounds__(256)
void gemm_tf32_nt(const float* __restrict__ A, const float* __restrict__ B,
                  float* __restrict__ C, int M, int N, int K,
                  const float* __restrict__ bias)
{
    __shared__ unsigned As[GBM][GST];   // [m][k]
    __shared__ unsigned Bs[GBN][GST];   // [n][k]

    const int tid  = threadIdx.x;
    const int lane = tid & 31;
    const int warp = tid >> 5;
    const int wm   = (warp >> 2) * 64;
    const int wn   = (warp & 3) * 32;
    const int m0   = blockIdx.y * GBM;
    const int n0   = blockIdx.x * GBN;
    const int lg   = lane >> 2;   // group id 0..7
    const int lt   = lane & 3;    // thread in group
    const int t8   = lane >> 3;   // ldmatrix matrix id 0..3
    const int rr   = lane & 7;    // ldmatrix row id 0..7

    const unsigned sA = (unsigned)__cvta_generic_to_shared(&As[0][0]);
    const unsigned sB = (unsigned)__cvta_generic_to_shared(&Bs[0][0]);

    // per-thread ldmatrix base addresses (byte)
    // A frag order: m0=(rowblk,colblk0) m1=(rowblk+8,0) m2=(rowblk,+4) m3=(+8,+4)
    unsigned aab[4];
#pragma unroll
    for (int mt = 0; mt < 4; mt++)
        aab[mt] = sA + 4u * ((wm + mt * 16 + (t8 & 1) * 8 + rr) * GST + (t8 >> 1) * 4);
    // B frag pairs: m0=bf[nt][0] m1=bf[nt][1] m2=bf[nt+1][0] m3=bf[nt+1][1]
    unsigned bbb[2];
#pragma unroll
    for (int ntp = 0; ntp < 2; ntp++)
        bbb[ntp] = sB + 4u * ((wn + (ntp * 2 + (t8 >> 1)) * 8 + rr) * GST + (t8 & 1) * 4);

    float acc[4][4][4];
#pragma unroll
    for (int mt = 0; mt < 4; mt++)
#pragma unroll
        for (int nt = 0; nt < 4; nt++)
#pragma unroll
            for (int j = 0; j < 4; j++) acc[mt][nt][j] = 0.f;

    for (int k0 = 0; k0 < K; k0 += GBK) {
#pragma unroll
        for (int i = 0; i < 4; i++) {
            int e  = tid + i * 256;
            int r  = e >> 3;
            int kq = (e & 7) << 2;
            float4 va = *(const float4*)&A[(size_t)(m0 + r) * K + k0 + kq];
            *(uint4*)&As[r][kq] = make_uint4(f2tf(va.x), f2tf(va.y), f2tf(va.z), f2tf(va.w));
            float4 vb = *(const float4*)&B[(size_t)(n0 + r) * K + k0 + kq];
            *(uint4*)&Bs[r][kq] = make_uint4(f2tf(vb.x), f2tf(vb.y), f2tf(vb.z), f2tf(vb.w));
        }
        __syncthreads();

#pragma unroll
        for (int ks = 0; ks < GBK; ks += 8) {
            unsigned af[4][4], bf[2][4];
#pragma unroll
            for (int mt = 0; mt < 4; mt++) ldsm4(af[mt], aab[mt] + ks * 4);
#pragma unroll
            for (int ntp = 0; ntp < 2; ntp++) ldsm4(bf[ntp], bbb[ntp] + ks * 4);
#pragma unroll
            for (int mt = 0; mt < 4; mt++)
#pragma unroll
                for (int nt = 0; nt < 4; nt++)
                    mma_tf32(acc[mt][nt], af[mt], &bf[nt >> 1][(nt & 1) * 2]);
        }
        __syncthreads();
    }

#pragma unroll
    for (int mt = 0; mt < 4; mt++) {
#pragma unroll
        for (int nt = 0; nt < 4; nt++) {
            int r = m0 + wm + mt * 16 + lg;
            int c = n0 + wn + nt * 8 + (lt << 1);
            float b0 = bias ? bias[c] : 0.f;
            float b1 = bias ? bias[c + 1] : 0.f;
            float2 v0 = make_float2(acc[mt][nt][0] + b0, acc[mt][nt][1] + b1);
            float2 v1 = make_float2(acc[mt][nt][2] + b0, acc[mt][nt][3] + b1);
            *(float2*)&C[(size_t)r * N + c]       = v0;
            *(float2*)&C[(size_t)(r + 8) * N + c] = v1;
        }
    }
}

// ---------------------------------------------------------------------------
// RoPE cos/sin table
// ---------------------------------------------------------------------------
__global__ void rope_table()
{
    int idx = blockIdx.x * blockDim.x + threadIdx.x;  // over SEQ*32
    if (idx >= SEQ * 32) return;
    int i = idx & 31;
    int n = idx >> 5;
    float inv_freq = (float)pow(10000.0, -(double)i / 32.0);
    float phase = (float)n * inv_freq;
    g_cos[idx] = (float)cos((double)phase);
    g_sin[idx] = (float)sin((double)phase);
}

// ---------------------------------------------------------------------------
// RoPE + transpose: qkv [4096, 3072] -> Q,K (roped), V  in [B,H,N,D]
// ---------------------------------------------------------------------------
__global__ void rope_transpose(const float* __restrict__ qkv,
                               float* __restrict__ Q, float* __restrict__ K,
                               float* __restrict__ V)
{
    int idx = blockIdx.x * blockDim.x + threadIdx.x;   // over B*H*N*D
    if (idx >= BATCH * HEADS * SEQ * HD) return;
    int d = idx & (HD - 1);
    int n = (idx >> 6) & (SEQ - 1);
    int h = (idx >> 17) & (HEADS - 1);
    int b = idx >> 21;

    const size_t mrow = (size_t)(b * SEQ + n) * (3 * C_DIM);
    const int col = h * HD + d;

    float qv = qkv[mrow + col];
    float kv = qkv[mrow + C_DIM + col];
    float vv = qkv[mrow + 2 * C_DIM + col];

    int i = d & 31;
    float c = g_cos[n * 32 + i];
    float s = g_sin[n * 32 + i];

    float qp = (d < 32) ? -qkv[mrow + col + 32] : qkv[mrow + col - 32];
    float kp = (d < 32) ? -qkv[mrow + C_DIM + col + 32] : qkv[mrow + C_DIM + col - 32];

    size_t o = ((size_t)(b * HEADS + h) * SEQ + n) * HD + d;
    Q[o] = qv * c + qp * s;
    K[o] = kv * c + kp * s;
    V[o] = vv;
}

// ---------------------------------------------------------------------------
// Flash attention v3 (tf32 mma + ldmatrix fragment loads):
//  - 128 Q rows/block, 8 warps; 64-row KV tiles
//  - Q/K smem [row][d] stride 68 (272B rows: 16B aligned, conflict-free ldmatrix)
//  - V stored TRANSPOSED VT[d][n] stride 68 with 16B-group XOR swizzle (g ^= d>>2)
//  - P accumulator -> A-fragment via shfl (no smem)
// ---------------------------------------------------------------------------
#define QTILE 128
#define KTILE 64
#define QKST  68
#define ATTN_SMEM_BYTES ((QTILE*QKST + KTILE*QKST + KTILE*QKST) * 4)

__global__ __launch_bounds__(256)
void attn_tf32(const float* __restrict__ Q, const float* __restrict__ K,
               const float* __restrict__ V, float* __restrict__ Out)
{
    extern __shared__ unsigned sm[];
    unsigned* Qs  = sm;                       // [128][68] row=q, col=d
    unsigned* Ks  = Qs + QTILE * QKST;        // [64][68]  row=kv, col=d
    unsigned* VTs = Ks + KTILE * QKST;        // [64][68]  row=d, col=n (swizzled)

    const int tid  = threadIdx.x;
    const int lane = tid & 31;
    const int warp = tid >> 5;
    const int lg   = lane >> 2;
    const int lt   = lane & 3;
    const int t8   = lane >> 3;
    const int rr   = lane & 7;
    const int b = blockIdx.z, h = blockIdx.y;
    const int q0 = blockIdx.x * QTILE;
    const int qr = warp * 16;                 // warp's q-row base in tile

    const unsigned sbase = (unsigned)__cvta_generic_to_shared(sm);
    const unsigned sK  = sbase + 4u * QTILE * QKST;
    const unsigned sVT = sK + 4u * KTILE * QKST;

    const float* Qb = Q + (size_t)(b * HEADS + h) * SEQ * HD;
    const float* Kb = K + (size_t)(b * HEADS + h) * SEQ * HD;
    const float* Vb = V + (size_t)(b * HEADS + h) * SEQ * HD;

    // Load Q tile (cvt to tf32)
#pragma unroll
    for (int i = 0; i < 8; i++) {
        int e = tid + i * 256;
        int r = e >> 4, c4 = (e & 15) << 2;
        float4 v = *(const float4*)&Qb[(size_t)(q0 + r) * HD + c4];
        *(uint4*)&Qs[r * QKST + c4] =
            make_uint4(f2tf(v.x), f2tf(v.y), f2tf(v.z), f2tf(v.w));
    }

    // ldmatrix base addresses
    // A (Q): m0=(row,col0) m1=(row+8,col0) m2=(row,col+4) m3=(row+8,col+4)
    const unsigned aQb = sbase + 4u * ((qr + (t8 & 1) * 8 + rr) * QKST + (t8 >> 1) * 4);
    // K pairs: m0=bf[nt][0] m1=bf[nt][1] m2=bf[nt+1][0] m3=bf[nt+1][1]
    unsigned kb[4];
#pragma unroll
    for (int ntp = 0; ntp < 4; ntp++)
        kb[ntp] = sK + 4u * (((ntp * 2 + (t8 >> 1)) * 8 + rr) * QKST + (t8 & 1) * 4);
    // VT pairs: row d = (nt + t8/2)*8 + rr; swizzled group = (2ks + (t8&1)) ^ (d>>2)
    unsigned vrowb[4], vsw[4];
#pragma unroll
    for (int ntp = 0; ntp < 4; ntp++) {
        int d = (ntp * 2 + (t8 >> 1)) * 8 + rr;
        vrowb[ntp] = sVT + (unsigned)(d * QKST * 4);
        vsw[ntp]   = (unsigned)(d >> 2);
    }

    float o[8][4];
#pragma unroll
    for (int nt = 0; nt < 8; nt++)
#pragma unroll
        for (int j = 0; j < 4; j++) o[nt][j] = 0.f;
    float m_lo = -1e30f, m_hi = -1e30f, l_lo = 0.f, l_hi = 0.f;

    __syncthreads();

    const int psrc = lg * 4 + (lt >> 1);     // shuffle source lane
    const bool podd = (lt & 1);

    for (int k0 = 0; k0 < SEQ; k0 += KTILE) {
        // Load K [kv][d]; V transposed into VT[d][n] with XOR swizzle
#pragma unroll
        for (int i = 0; i < 4; i++) {
            int e = tid + i * 256;
            int r = e >> 4, c4 = (e & 15) << 2;    // r = kv row, c4 = d base
            float4 kv = *(const float4*)&Kb[(size_t)(k0 + r) * HD + c4];
            *(uint4*)&Ks[r * QKST + c4] =
                make_uint4(f2tf(kv.x), f2tf(kv.y), f2tf(kv.z), f2tf(kv.w));
            float4 vv = *(const float4*)&Vb[(size_t)(k0 + r) * HD + c4];
            int grp = ((r >> 2) ^ (c4 >> 2)) << 2;  // d>>2 == c4>>2 for all 4
            int w   = r & 3;
            VTs[(c4 + 0) * QKST + grp + w] = f2tf(vv.x);
            VTs[(c4 + 1) * QKST + grp + w] = f2tf(vv.y);
            VTs[(c4 + 2) * QKST + grp + w] = f2tf(vv.z);
            VTs[(c4 + 3) * QKST + grp + w] = f2tf(vv.w);
        }
        __syncthreads();

        // ---- S = Q K^T  (warp: 16 x 64) ----
        float s[8][4];
#pragma unroll
        for (int nt = 0; nt < 8; nt++)
#pragma unroll
            for (int j = 0; j < 4; j++) s[nt][j] = 0.f;

#pragma unroll
        for (int ks = 0; ks < 8; ks++) {
            unsigned af[4];
            ldsm4(af, aQb + ks * 32);
#pragma unroll
            for (int ntp = 0; ntp < 4; ntp++) {
                unsigned kf[4];
                ldsm4(kf, kb[ntp] + ks * 32);
                mma_tf32(s[ntp * 2],     af, &kf[0]);
                mma_tf32(s[ntp * 2 + 1], af, &kf[2]);
            }
        }

        // ---- online softmax on fragments ----
        const float scale = 0.125f;
        float rmax_lo = -1e30f, rmax_hi = -1e30f;
#pragma unroll
        for (int nt = 0; nt < 8; nt++) {
            s[nt][0] *= scale; s[nt][1] *= scale;
            s[nt][2] *= scale; s[nt][3] *= scale;
            rmax_lo = fmaxf(rmax_lo, fmaxf(s[nt][0], s[nt][1]));
            rmax_hi = fmaxf(rmax_hi, fmaxf(s[nt][2], s[nt][3]));
        }
        rmax_lo = fmaxf(rmax_lo, __shfl_xor_sync(0xffffffffu, rmax_lo, 1));
        rmax_lo = fmaxf(rmax_lo, __shfl_xor_sync(0xffffffffu, rmax_lo, 2));
        rmax_hi = fmaxf(rmax_hi, __shfl_xor_sync(0xffffffffu, rmax_hi, 1));
        rmax_hi = fmaxf(rmax_hi, __shfl_xor_sync(0xffffffffu, rmax_hi, 2));

        float mn_lo = fmaxf(m_lo, rmax_lo);
        float mn_hi = fmaxf(m_hi, rmax_hi);
        float alpha_lo = __expf(m_lo - mn_lo);
        float alpha_hi = __expf(m_hi - mn_hi);
        m_lo = mn_lo; m_hi = mn_hi;

        float sum_lo = 0.f, sum_hi = 0.f;
#pragma unroll
        for (int nt = 0; nt < 8; nt++) {
            s[nt][0] = __expf(s[nt][0] - m_lo);
            s[nt][1] = __expf(s[nt][1] - m_lo);
            s[nt][2] = __expf(s[nt][2] - m_hi);
            s[nt][3] = __expf(s[nt][3] - m_hi);
            sum_lo += s[nt][0] + s[nt][1];
            sum_hi += s[nt][2] + s[nt][3];
            o[nt][0] *= alpha_lo; o[nt][1] *= alpha_lo;
            o[nt][2] *= alpha_hi; o[nt][3] *= alpha_hi;
        }
        sum_lo += __shfl_xor_sync(0xffffffffu, sum_lo, 1);
        sum_lo += __shfl_xor_sync(0xffffffffu, sum_lo, 2);
        sum_hi += __shfl_xor_sync(0xffffffffu, sum_hi, 1);
        sum_hi += __shfl_xor_sync(0xffffffffu, sum_hi, 2);
        l_lo = l_lo * alpha_lo + sum_lo;
        l_hi = l_hi * alpha_hi + sum_hi;

        // ---- O += P V : P accumulator -> A-fragment via shfl, V via ldmatrix ----
#pragma unroll
        for (int ks = 0; ks < 8; ks++) {
            float e0  = __shfl_sync(0xffffffffu, s[ks][0], psrc);
            float q0v = __shfl_sync(0xffffffffu, s[ks][1], psrc);
            float e1  = __shfl_sync(0xffffffffu, s[ks][2], psrc);
            float q1v = __shfl_sync(0xffffffffu, s[ks][3], psrc);
            float e2  = __shfl_sync(0xffffffffu, s[ks][0], psrc + 2);
            float q2v = __shfl_sync(0xffffffffu, s[ks][1], psrc + 2);
            float e3  = __shfl_sync(0xffffffffu, s[ks][2], psrc + 2);
            float q3v = __shfl_sync(0xffffffffu, s[ks][3], psrc + 2);
            unsigned pf[4];
            pf[0] = f2tf(podd ? q0v : e0);   // P[lg   ][8ks+lt  ]
            pf[1] = f2tf(podd ? q1v : e1);   // P[lg+8 ][8ks+lt  ]
            pf[2] = f2tf(podd ? q2v : e2);   // P[lg   ][8ks+lt+4]
            pf[3] = f2tf(podd ? q3v : e3);   // P[lg+8 ][8ks+lt+4]

            unsigned gk = (unsigned)(2 * ks + (t8 & 1));
#pragma unroll
            for (int ntp = 0; ntp < 4; ntp++) {
                unsigned vf[4];
                ldsm4(vf, vrowb[ntp] + ((gk ^ vsw[ntp]) << 4));
                mma_tf32(o[ntp * 2],     pf, &vf[0]);
                mma_tf32(o[ntp * 2 + 1], pf, &vf[2]);
            }
        }
        __syncthreads();
    }

    // ---- epilogue: normalize, write [B, N, H*D] ----
    float inv_lo = 1.0f / l_lo;
    float inv_hi = 1.0f / l_hi;
#pragma unroll
    for (int nt = 0; nt < 8; nt++) {
        int r = q0 + qr + lg;
        int c = h * HD + nt * 8 + (lt << 1);
        float2 v0 = make_float2(o[nt][0] * inv_lo, o[nt][1] * inv_lo);
        float2 v1 = make_float2(o[nt][2] * inv_hi, o[nt][3] * inv_hi);
        *(float2*)&Out[(size_t)(b * SEQ + r) * C_DIM + c]     = v0;
        *(float2*)&Out[(size_t)(b * SEQ + r + 8) * C_DIM + c] = v1;
    }
}

// ---------------------------------------------------------------------------
extern "C" void kernel_launch(void* const* d_in, const int* in_sizes, int n_in,
                              void* d_out, int out_size)
{
    const float* x    = (const float*)d_in[0];   // [2,2048,1024]
    const float* Wqkv = (const float*)d_in[1];   // [3072,1024]
    const float* Wout = (const float*)d_in[2];   // [1024,1024]
    const float* bout = (const float*)d_in[3];   // [1024]
    float* out = (float*)d_out;                  // [2,2048,1024]

    float *qkv, *Q, *K, *V, *attn;
    cudaGetSymbolAddress((void**)&qkv,  g_qkv);
    cudaGetSymbolAddress((void**)&Q,    g_Q);
    cudaGetSymbolAddress((void**)&K,    g_K);
    cudaGetSymbolAddress((void**)&V,    g_V);
    cudaGetSymbolAddress((void**)&attn, g_attn);

    // 0) RoPE tables
    rope_table<<<(SEQ * 32 + 255) / 256, 256>>>();

    // 1) QKV projection (tf32): [4096,3072] = x @ Wqkv^T
    gemm_tf32_nt<<<dim3(3 * C_DIM / GBN, M_ROWS / GBM), 256>>>(
        x, Wqkv, qkv, M_ROWS, 3 * C_DIM, C_DIM, nullptr);

    // 2) RoPE + transpose into [B,H,N,D]
    {
        int total = BATCH * HEADS * SEQ * HD;
        rope_transpose<<<(total + 255) / 256, 256>>>(qkv, Q, K, V);
    }

    // 3) Flash attention v3 (tf32 mma + ldmatrix) -> [B,N,C]
    cudaFuncSetAttribute(attn_tf32,
                         cudaFuncAttributeMaxDynamicSharedMemorySize,
                         ATTN_SMEM_BYTES);
    attn_tf32<<<dim3(SEQ / QTILE, HEADS, BATCH), 256, ATTN_SMEM_BYTES>>>(
        Q, K, V, attn);

    // 4) Output projection (tf32): out = attn @ Wout^T + bout
    gemm_tf32_nt<<<dim3(C_DIM / GBN, M_ROWS / GBM), 256>>>(
        attn, Wout, out, M_ROWS, C_DIM, C_DIM, bout);
}

// round 5
// speedup vs baseline: 1.0542x; 1.0542x over previous
#include <cuda_runtime.h>
#include <math.h>

// Problem constants
#define C_DIM   1024
#define HEADS   16
#define HD      64
#define BATCH   2
#define SEQ     2048
#define M_ROWS  (BATCH*SEQ)        // 4096

// Scratch (device globals: no allocation allowed)
__device__ float g_qkv[(size_t)M_ROWS * 3 * C_DIM];          // [4096, 3072]
__device__ float g_Q[(size_t)BATCH*HEADS*SEQ*HD];            // [B,H,N,D]
__device__ float g_K[(size_t)BATCH*HEADS*SEQ*HD];
__device__ float g_V[(size_t)BATCH*HEADS*SEQ*HD];
__device__ float g_attn[(size_t)M_ROWS * C_DIM];             // [B,N,H*D]
__device__ float g_cos[SEQ * 32];
__device__ float g_sin[SEQ * 32];

// ---------------------------------------------------------------------------
// tf32 / ldmatrix helpers
// ---------------------------------------------------------------------------
__device__ __forceinline__ unsigned f2tf(float x) {
    unsigned r;
    asm("cvt.rna.tf32.f32 %0, %1;" : "=r"(r) : "f"(x));
    return r;
}

__device__ __forceinline__ void mma_tf32(float* d, const unsigned* a, const unsigned* b) {
    asm volatile(
        "mma.sync.aligned.m16n8k8.row.col.f32.tf32.tf32.f32 "
        "{%0,%1,%2,%3}, {%4,%5,%6,%7}, {%8,%9}, {%0,%1,%2,%3};\n"
        : "+f"(d[0]), "+f"(d[1]), "+f"(d[2]), "+f"(d[3])
        : "r"(a[0]), "r"(a[1]), "r"(a[2]), "r"(a[3]), "r"(b[0]), "r"(b[1]));
}

// ldmatrix x4: lane L supplies address for matrix L/8, row L%8 (16B rows).
__device__ __forceinline__ void ldsm4(unsigned* r, unsigned addr) {
    asm volatile(
        "ldmatrix.sync.aligned.m8n8.x4.shared.b16 {%0,%1,%2,%3}, [%4];"
        : "=r"(r[0]), "=r"(r[1]), "=r"(r[2]), "=r"(r[3]) : "r"(addr));
}

// ---------------------------------------------------------------------------
// tf32 GEMM (NT): C[M,N] = A[M,K] * B[N,K]^T (+ bias)
// Block 128x128, BK=32, 256 threads (8 warps: 2m x 4n, warp tile 64x32)
// Fragments gathered with ldmatrix.x4.
// ---------------------------------------------------------------------------
#define GBM 128
#define GBN 128
#define GBK 32
#define GPAD 4
#define GST  (GBK + GPAD)    // 36 words -> 144B rows: 16B aligned, conflict-free

__global__ __launch_bounds__(256)
void gemm_tf32_nt(const float* __restrict__ A, const float* __restrict__ B,
                  float* __restrict__ C, int M, int N, int K,
                  const float* __restrict__ bias)
{
    __shared__ unsigned As[GBM][GST];   // [m][k]
    __shared__ unsigned Bs[GBN][GST];   // [n][k]

    const int tid  = threadIdx.x;
    const int lane = tid & 31;
    const int warp = tid >> 5;
    const int wm   = (warp >> 2) * 64;
    const int wn   = (warp & 3) * 32;
    const int m0   = blockIdx.y * GBM;
    const int n0   = blockIdx.x * GBN;
    const int lg   = lane >> 2;   // group id 0..7
    const int lt   = lane & 3;    // thread in group
    const int t8   = lane >> 3;   // ldmatrix matrix id 0..3
    const int rr   = lane & 7;    // ldmatrix row id 0..7

    const unsigned sA = (unsigned)__cvta_generic_to_shared(&As[0][0]);
    const unsigned sB = (unsigned)__cvta_generic_to_shared(&Bs[0][0]);

    unsigned aab[4];
#pragma unroll
    for (int mt = 0; mt < 4; mt++)
        aab[mt] = sA + 4u * ((wm + mt * 16 + (t8 & 1) * 8 + rr) * GST + (t8 >> 1) * 4);
    unsigned bbb[2];
#pragma unroll
    for (int ntp = 0; ntp < 2; ntp++)
        bbb[ntp] = sB + 4u * ((wn + (ntp * 2 + (t8 >> 1)) * 8 + rr) * GST + (t8 & 1) * 4);

    float acc[4][4][4];
#pragma unroll
    for (int mt = 0; mt < 4; mt++)
#pragma unroll
        for (int nt = 0; nt < 4; nt++)
#pragma unroll
            for (int j = 0; j < 4; j++) acc[mt][nt][j] = 0.f;

    for (int k0 = 0; k0 < K; k0 += GBK) {
#pragma unroll
        for (int i = 0; i < 4; i++) {
            int e  = tid + i * 256;
            int r  = e >> 3;
            int kq = (e & 7) << 2;
            float4 va = *(const float4*)&A[(size_t)(m0 + r) * K + k0 + kq];
            *(uint4*)&As[r][kq] = make_uint4(f2tf(va.x), f2tf(va.y), f2tf(va.z), f2tf(va.w));
            float4 vb = *(const float4*)&B[(size_t)(n0 + r) * K + k0 + kq];
            *(uint4*)&Bs[r][kq] = make_uint4(f2tf(vb.x), f2tf(vb.y), f2tf(vb.z), f2tf(vb.w));
        }
        __syncthreads();

#pragma unroll
        for (int ks = 0; ks < GBK; ks += 8) {
            unsigned af[4][4], bf[2][4];
#pragma unroll
            for (int mt = 0; mt < 4; mt++) ldsm4(af[mt], aab[mt] + ks * 4);
#pragma unroll
            for (int ntp = 0; ntp < 2; ntp++) ldsm4(bf[ntp], bbb[ntp] + ks * 4);
#pragma unroll
            for (int mt = 0; mt < 4; mt++)
#pragma unroll
                for (int nt = 0; nt < 4; nt++)
                    mma_tf32(acc[mt][nt], af[mt], &bf[nt >> 1][(nt & 1) * 2]);
        }
        __syncthreads();
    }

#pragma unroll
    for (int mt = 0; mt < 4; mt++) {
#pragma unroll
        for (int nt = 0; nt < 4; nt++) {
            int r = m0 + wm + mt * 16 + lg;
            int c = n0 + wn + nt * 8 + (lt << 1);
            float b0 = bias ? bias[c] : 0.f;
            float b1 = bias ? bias[c + 1] : 0.f;
            float2 v0 = make_float2(acc[mt][nt][0] + b0, acc[mt][nt][1] + b1);
            float2 v1 = make_float2(acc[mt][nt][2] + b0, acc[mt][nt][3] + b1);
            *(float2*)&C[(size_t)r * N + c]       = v0;
            *(float2*)&C[(size_t)(r + 8) * N + c] = v1;
        }
    }
}

// ---------------------------------------------------------------------------
// RoPE cos/sin table
// ---------------------------------------------------------------------------
__global__ void rope_table()
{
    int idx = blockIdx.x * blockDim.x + threadIdx.x;  // over SEQ*32
    if (idx >= SEQ * 32) return;
    int i = idx & 31;
    int n = idx >> 5;
    float inv_freq = (float)pow(10000.0, -(double)i / 32.0);
    float phase = (float)n * inv_freq;
    g_cos[idx] = (float)cos((double)phase);
    g_sin[idx] = (float)sin((double)phase);
}

// ---------------------------------------------------------------------------
// RoPE + transpose: qkv [4096, 3072] -> Q,K (roped), V  in [B,H,N,D]
// ---------------------------------------------------------------------------
__global__ void rope_transpose(const float* __restrict__ qkv,
                               float* __restrict__ Q, float* __restrict__ K,
                               float* __restrict__ V)
{
    int idx = blockIdx.x * blockDim.x + threadIdx.x;   // over B*H*N*D
    if (idx >= BATCH * HEADS * SEQ * HD) return;
    int d = idx & (HD - 1);
    int n = (idx >> 6) & (SEQ - 1);
    int h = (idx >> 17) & (HEADS - 1);
    int b = idx >> 21;

    const size_t mrow = (size_t)(b * SEQ + n) * (3 * C_DIM);
    const int col = h * HD + d;

    float qv = qkv[mrow + col];
    float kv = qkv[mrow + C_DIM + col];
    float vv = qkv[mrow + 2 * C_DIM + col];

    int i = d & 31;
    float c = g_cos[n * 32 + i];
    float s = g_sin[n * 32 + i];

    float qp = (d < 32) ? -qkv[mrow + col + 32] : qkv[mrow + col - 32];
    float kp = (d < 32) ? -qkv[mrow + C_DIM + col + 32] : qkv[mrow + C_DIM + col - 32];

    size_t o = ((size_t)(b * HEADS + h) * SEQ + n) * HD + d;
    Q[o] = qv * c + qp * s;
    K[o] = kv * c + kp * s;
    V[o] = vv;
}

// ---------------------------------------------------------------------------
// Flash attention v4 (tf32 mma + ldmatrix, 2 blocks/SM enforced):
//  - 128 Q rows/block, 8 warps; 64-row KV tiles
//  - softmax scale folded into Q at load (0.125 = 2^-3, exact)
//  - Q/K smem [row][d] stride 68; V transposed VT[d][n] stride 68, XOR swizzle
//  - P accumulator -> A-fragment via shfl (no smem)
// ---------------------------------------------------------------------------
#define QTILE 128
#define KTILE 64
#define QKST  68
#define ATTN_SMEM_BYTES ((QTILE*QKST + KTILE*QKST + KTILE*QKST) * 4)

__global__ __launch_bounds__(256, 2)
void attn_tf32(const float* __restrict__ Q, const float* __restrict__ K,
               const float* __restrict__ V, float* __restrict__ Out)
{
    extern __shared__ unsigned sm[];
    unsigned* Qs  = sm;                       // [128][68] row=q, col=d
    unsigned* Ks  = Qs + QTILE * QKST;        // [64][68]  row=kv, col=d
    unsigned* VTs = Ks + KTILE * QKST;        // [64][68]  row=d, col=n (swizzled)

    const int tid  = threadIdx.x;
    const int lane = tid & 31;
    const int warp = tid >> 5;
    const int lg   = lane >> 2;
    const int lt   = lane & 3;
    const int t8   = lane >> 3;
    const int rr   = lane & 7;
    const int b = blockIdx.z, h = blockIdx.y;
    const int q0 = blockIdx.x * QTILE;
    const int qr = warp * 16;                 // warp's q-row base in tile

    const unsigned sbase = (unsigned)__cvta_generic_to_shared(sm);
    const unsigned sK  = sbase + 4u * QTILE * QKST;
    const unsigned sVT = sK + 4u * KTILE * QKST;

    const float* Qb = Q + (size_t)(b * HEADS + h) * SEQ * HD;
    const float* Kb = K + (size_t)(b * HEADS + h) * SEQ * HD;
    const float* Vb = V + (size_t)(b * HEADS + h) * SEQ * HD;

    // Load Q tile, pre-scaled by 1/sqrt(D) = 0.125 (exact power of two)
#pragma unroll
    for (int i = 0; i < 8; i++) {
        int e = tid + i * 256;
        int r = e >> 4, c4 = (e & 15) << 2;
        float4 v = *(const float4*)&Qb[(size_t)(q0 + r) * HD + c4];
        *(uint4*)&Qs[r * QKST + c4] =
            make_uint4(f2tf(v.x * 0.125f), f2tf(v.y * 0.125f),
                       f2tf(v.z * 0.125f), f2tf(v.w * 0.125f));
    }

    // ldmatrix base addresses
    const unsigned aQb = sbase + 4u * ((qr + (t8 & 1) * 8 + rr) * QKST + (t8 >> 1) * 4);
    const unsigned kb0 = sK + 4u * (((t8 >> 1) * 8 + rr) * QKST + (t8 & 1) * 4);
    const int vd0 = (t8 >> 1) * 8 + rr;       // d row for ntp=0
    const unsigned vb0 = sVT + (unsigned)(vd0 * QKST * 4);
    const unsigned vsw0 = (unsigned)(vd0 >> 2);

    float o[8][4];
#pragma unroll
    for (int nt = 0; nt < 8; nt++)
#pragma unroll
        for (int j = 0; j < 4; j++) o[nt][j] = 0.f;
    float m_lo = -1e30f, m_hi = -1e30f, l_lo = 0.f, l_hi = 0.f;

    __syncthreads();

    const int psrc = lg * 4 + (lt >> 1);     // shuffle source lane
    const bool podd = (lt & 1);

    for (int k0 = 0; k0 < SEQ; k0 += KTILE) {
        // Load K [kv][d]; V transposed into VT[d][n] with XOR swizzle
#pragma unroll
        for (int i = 0; i < 4; i++) {
            int e = tid + i * 256;
            int r = e >> 4, c4 = (e & 15) << 2;    // r = kv row, c4 = d base
            float4 kv = *(const float4*)&Kb[(size_t)(k0 + r) * HD + c4];
            *(uint4*)&Ks[r * QKST + c4] =
                make_uint4(f2tf(kv.x), f2tf(kv.y), f2tf(kv.z), f2tf(kv.w));
            float4 vv = *(const float4*)&Vb[(size_t)(k0 + r) * HD + c4];
            int grp = ((r >> 2) ^ (c4 >> 2)) << 2;
            int w   = r & 3;
            VTs[(c4 + 0) * QKST + grp + w] = f2tf(vv.x);
            VTs[(c4 + 1) * QKST + grp + w] = f2tf(vv.y);
            VTs[(c4 + 2) * QKST + grp + w] = f2tf(vv.z);
            VTs[(c4 + 3) * QKST + grp + w] = f2tf(vv.w);
        }
        __syncthreads();

        // ---- S = Q K^T  (warp: 16 x 64) ----
        float s[8][4];
#pragma unroll
        for (int nt = 0; nt < 8; nt++)
#pragma unroll
            for (int j = 0; j < 4; j++) s[nt][j] = 0.f;

#pragma unroll
        for (int ks = 0; ks < 8; ks++) {
            unsigned af[4];
            ldsm4(af, aQb + ks * 32);
#pragma unroll
            for (int ntp = 0; ntp < 4; ntp++) {
                unsigned kf[4];
                ldsm4(kf, kb0 + (unsigned)(ntp * 16 * QKST * 4) + ks * 32);
                mma_tf32(s[ntp * 2],     af, &kf[0]);
                mma_tf32(s[ntp * 2 + 1], af, &kf[2]);
            }
        }

        // ---- online softmax on fragments (S already scaled via Q) ----
        float rmax_lo = -1e30f, rmax_hi = -1e30f;
#pragma unroll
        for (int nt = 0; nt < 8; nt++) {
            rmax_lo = fmaxf(rmax_lo, fmaxf(s[nt][0], s[nt][1]));
            rmax_hi = fmaxf(rmax_hi, fmaxf(s[nt][2], s[nt][3]));
        }
        rmax_lo = fmaxf(rmax_lo, __shfl_xor_sync(0xffffffffu, rmax_lo, 1));
        rmax_lo = fmaxf(rmax_lo, __shfl_xor_sync(0xffffffffu, rmax_lo, 2));
        rmax_hi = fmaxf(rmax_hi, __shfl_xor_sync(0xffffffffu, rmax_hi, 1));
        rmax_hi = fmaxf(rmax_hi, __shfl_xor_sync(0xffffffffu, rmax_hi, 2));

        float mn_lo = fmaxf(m_lo, rmax_lo);
        float mn_hi = fmaxf(m_hi, rmax_hi);
        float alpha_lo = __expf(m_lo - mn_lo);
        float alpha_hi = __expf(m_hi - mn_hi);
        m_lo = mn_lo; m_hi = mn_hi;

        float sum_lo = 0.f, sum_hi = 0.f;
#pragma unroll
        for (int nt = 0; nt < 8; nt++) {
            s[nt][0] = __expf(s[nt][0] - m_lo);
            s[nt][1] = __expf(s[nt][1] - m_lo);
            s[nt][2] = __expf(s[nt][2] - m_hi);
            s[nt][3] = __expf(s[nt][3] - m_hi);
            sum_lo += s[nt][0] + s[nt][1];
            sum_hi += s[nt][2] + s[nt][3];
            o[nt][0] *= alpha_lo; o[nt][1] *= alpha_lo;
            o[nt][2] *= alpha_hi; o[nt][3] *= alpha_hi;
        }
        sum_lo += __shfl_xor_sync(0xffffffffu, sum_lo, 1);
        sum_lo += __shfl_xor_sync(0xffffffffu, sum_lo, 2);
        sum_hi += __shfl_xor_sync(0xffffffffu, sum_hi, 1);
        sum_hi += __shfl_xor_sync(0xffffffffu, sum_hi, 2);
        l_lo = l_lo * alpha_lo + sum_lo;
        l_hi = l_hi * alpha_hi + sum_hi;

        // ---- O += P V : P accumulator -> A-fragment via shfl, V via ldmatrix ----
#pragma unroll
        for (int ks = 0; ks < 8; ks++) {
            float e0  = __shfl_sync(0xffffffffu, s[ks][0], psrc);
            float q0v = __shfl_sync(0xffffffffu, s[ks][1], psrc);
            float e1  = __shfl_sync(0xffffffffu, s[ks][2], psrc);
            float q1v = __shfl_sync(0xffffffffu, s[ks][3], psrc);
            float e2  = __shfl_sync(0xffffffffu, s[ks][0], psrc + 2);
            float q2v = __shfl_sync(0xffffffffu, s[ks][1], psrc + 2);
            float e3  = __shfl_sync(0xffffffffu, s[ks][2], psrc + 2);
            float q3v = __shfl_sync(0xffffffffu, s[ks][3], psrc + 2);
            unsigned pf[4];
            pf[0] = f2tf(podd ? q0v : e0);
            pf[1] = f2tf(podd ? q1v : e1);
            pf[2] = f2tf(podd ? q2v : e2);
            pf[3] = f2tf(podd ? q3v : e3);

            unsigned gk = (unsigned)(2 * ks + (t8 & 1));
#pragma unroll
            for (int ntp = 0; ntp < 4; ntp++) {
                unsigned vf[4];
                unsigned sw = (gk ^ (vsw0 + 4u * ntp)) & 15u;
                ldsm4(vf, vb0 + (unsigned)(ntp * 16 * QKST * 4) + (sw << 4));
                mma_tf32(o[ntp * 2],     pf, &vf[0]);
                mma_tf32(o[ntp * 2 + 1], pf, &vf[2]);
            }
        }
        __syncthreads();
    }

    // ---- epilogue: normalize, write [B, N, H*D] ----
    float inv_lo = 1.0f / l_lo;
    float inv_hi = 1.0f / l_hi;
#pragma unroll
    for (int nt = 0; nt < 8; nt++) {
        int r = q0 + qr + lg;
        int c = h * HD + nt * 8 + (lt << 1);
        float2 v0 = make_float2(o[nt][0] * inv_lo, o[nt][1] * inv_lo);
        float2 v1 = make_float2(o[nt][2] * inv_hi, o[nt][3] * inv_hi);
        *(float2*)&Out[(size_t)(b * SEQ + r) * C_DIM + c]     = v0;
        *(float2*)&Out[(size_t)(b * SEQ + r + 8) * C_DIM + c] = v1;
    }
}

// ---------------------------------------------------------------------------
extern "C" void kernel_launch(void* const* d_in, const int* in_sizes, int n_in,
                              void* d_out, int out_size)
{
    const float* x    = (const float*)d_in[0];   // [2,2048,1024]
    const float* Wqkv = (const float*)d_in[1];   // [3072,1024]
    const float* Wout = (const float*)d_in[2];   // [1024,1024]
    const float* bout = (const float*)d_in[3];   // [1024]
    float* out = (float*)d_out;                  // [2,2048,1024]

    float *qkv, *Q, *K, *V, *attn;
    cudaGetSymbolAddress((void**)&qkv,  g_qkv);
    cudaGetSymbolAddress((void**)&Q,    g_Q);
    cudaGetSymbolAddress((void**)&K,    g_K);
    cudaGetSymbolAddress((void**)&V,    g_V);
    cudaGetSymbolAddress((void**)&attn, g_attn);

    // 0) RoPE tables
    rope_table<<<(SEQ * 32 + 255) / 256, 256>>>();

    // 1) QKV projection (tf32): [4096,3072] = x @ Wqkv^T
    gemm_tf32_nt<<<dim3(3 * C_DIM / GBN, M_ROWS / GBM), 256>>>(
        x, Wqkv, qkv, M_ROWS, 3 * C_DIM, C_DIM, nullptr);

    // 2) RoPE + transpose into [B,H,N,D]
    {
        int total = BATCH * HEADS * SEQ * HD;
        rope_transpose<<<(total + 255) / 256, 256>>>(qkv, Q, K, V);
    }

    // 3) Flash attention v4 (tf32 mma + ldmatrix, occ-capped) -> [B,N,C]
    cudaFuncSetAttribute(attn_tf32,
                         cudaFuncAttributeMaxDynamicSharedMemorySize,
                         ATTN_SMEM_BYTES);
    attn_tf32<<<dim3(SEQ / QTILE, HEADS, BATCH), 256, ATTN_SMEM_BYTES>>>(
        Q, K, V, attn);

    // 4) Output projection (tf32): out = attn @ Wout^T + bout
    gemm_tf32_nt<<<dim3(C_DIM / GBN, M_ROWS / GBM), 256>>>(
        attn, Wout, out, M_ROWS, C_DIM, C_DIM, bout);
}

// round 6
// speedup vs baseline: 1.2177x; 1.1551x over previous
#include <cuda_runtime.h>
#include <math.h>

// Problem constants
#define C_DIM   1024
#define HEADS   16
#define HD      64
#define BATCH   2
#define SEQ     2048
#define M_ROWS  (BATCH*SEQ)        // 4096

// Scratch (device globals: no allocation allowed)
__device__ float g_qkv[(size_t)M_ROWS * 3 * C_DIM];          // [4096, 3072]
__device__ float g_Q[(size_t)BATCH*HEADS*SEQ*HD];            // [B,H,N,D] tf32-rounded
__device__ float g_K[(size_t)BATCH*HEADS*SEQ*HD];
__device__ float g_V[(size_t)BATCH*HEADS*SEQ*HD];
__device__ float g_attn[(size_t)M_ROWS * C_DIM];             // [B,N,H*D] tf32-rounded
__device__ float g_xtf[(size_t)M_ROWS * C_DIM];              // x rounded to tf32
__device__ float g_wqkv[(size_t)3 * C_DIM * C_DIM];          // Wqkv rounded
__device__ float g_wout[(size_t)C_DIM * C_DIM];              // Wout rounded
__device__ float g_cos[SEQ * 32];
__device__ float g_sin[SEQ * 32];

// ---------------------------------------------------------------------------
// tf32 / ldmatrix / cp.async helpers
// ---------------------------------------------------------------------------
__device__ __forceinline__ unsigned f2tf(float x) {
    unsigned r;
    asm("cvt.rna.tf32.f32 %0, %1;" : "=r"(r) : "f"(x));
    return r;
}
__device__ __forceinline__ float f2tff(float x) { return __uint_as_float(f2tf(x)); }

__device__ __forceinline__ void mma_tf32(float* d, const unsigned* a, const unsigned* b) {
    asm volatile(
        "mma.sync.aligned.m16n8k8.row.col.f32.tf32.tf32.f32 "
        "{%0,%1,%2,%3}, {%4,%5,%6,%7}, {%8,%9}, {%0,%1,%2,%3};\n"
        : "+f"(d[0]), "+f"(d[1]), "+f"(d[2]), "+f"(d[3])
        : "r"(a[0]), "r"(a[1]), "r"(a[2]), "r"(a[3]), "r"(b[0]), "r"(b[1]));
}

__device__ __forceinline__ void ldsm4(unsigned* r, unsigned addr) {
    asm volatile(
        "ldmatrix.sync.aligned.m8n8.x4.shared.b16 {%0,%1,%2,%3}, [%4];"
        : "=r"(r[0]), "=r"(r[1]), "=r"(r[2]), "=r"(r[3]) : "r"(addr));
}

__device__ __forceinline__ void cp_async16(unsigned saddr, const void* gaddr) {
    asm volatile("cp.async.cg.shared.global [%0], [%1], 16;" :: "r"(saddr), "l"(gaddr));
}
#define CP_COMMIT() asm volatile("cp.async.commit_group;")
#define CP_WAIT0()  asm volatile("cp.async.wait_group 0;")

// ---------------------------------------------------------------------------
// Elementwise tf32 rounding (operands pre-rounded once; GEMM hot loop has 0 cvt)
// ---------------------------------------------------------------------------
__global__ void round_tf32(const float4* __restrict__ in, float4* __restrict__ out, int n4)
{
    int i = blockIdx.x * blockDim.x + threadIdx.x;
    if (i < n4) {
        float4 v = in[i];
        out[i] = make_float4(f2tff(v.x), f2tff(v.y), f2tff(v.z), f2tff(v.w));
    }
}

// ---------------------------------------------------------------------------
// tf32 GEMM (NT), cp.async 2-stage double-buffered, ldmatrix fragments.
// Operands MUST already be tf32-rounded. C[M,N] = A[M,K]*B[N,K]^T (+bias)
// Block 128x128, BK=32, 256 threads (8 warps: 2m x 4n)
// ---------------------------------------------------------------------------
#define GBM 128
#define GBN 128
#define GBK 32
#define GST 36                       // 144B rows: 16B aligned, conflict-free
#define GSTAGE_BYTES ((GBM + GBN) * GST * 4)
#define GEMM_SMEM_BYTES (2 * GSTAGE_BYTES)   // 73728

__global__ __launch_bounds__(256, 2)
void gemm_tf32_db(const float* __restrict__ A, const float* __restrict__ B,
                  float* __restrict__ C, int M, int N, int K,
                  const float* __restrict__ bias)
{
    extern __shared__ unsigned gsm[];

    const int tid  = threadIdx.x;
    const int lane = tid & 31;
    const int warp = tid >> 5;
    const int wm   = (warp >> 2) * 64;
    const int wn   = (warp & 3) * 32;
    const int m0   = blockIdx.y * GBM;
    const int n0   = blockIdx.x * GBN;
    const int lg   = lane >> 2;
    const int lt   = lane & 3;
    const int t8   = lane >> 3;
    const int rr   = lane & 7;

    const unsigned sA = (unsigned)__cvta_generic_to_shared(gsm);
    const unsigned sB = sA + GBM * GST * 4;

    unsigned aab[4];
#pragma unroll
    for (int mt = 0; mt < 4; mt++)
        aab[mt] = sA + 4u * ((wm + mt * 16 + (t8 & 1) * 8 + rr) * GST + (t8 >> 1) * 4);
    unsigned bbb[2];
#pragma unroll
    for (int ntp = 0; ntp < 2; ntp++)
        bbb[ntp] = sB + 4u * ((wn + (ntp * 2 + (t8 >> 1)) * 8 + rr) * GST + (t8 & 1) * 4);

    // per-thread load slots: e = tid + i*256 -> row e>>3, kq (e&7)*4
    float acc[4][4][4];
#pragma unroll
    for (int mt = 0; mt < 4; mt++)
#pragma unroll
        for (int nt = 0; nt < 4; nt++)
#pragma unroll
            for (int j = 0; j < 4; j++) acc[mt][nt][j] = 0.f;

    const int T = K / GBK;

    // prefetch tile 0 into stage 0
    {
        unsigned soff = 0;
#pragma unroll
        for (int i = 0; i < 4; i++) {
            int e = tid + i * 256;
            int r = e >> 3, kq = (e & 7) << 2;
            cp_async16(sA + soff + 4u * (r * GST + kq), &A[(size_t)(m0 + r) * K + kq]);
            cp_async16(sB + soff + 4u * (r * GST + kq), &B[(size_t)(n0 + r) * K + kq]);
        }
        CP_COMMIT();
    }

    for (int t = 0; t < T; t++) {
        const unsigned soff = (unsigned)(t & 1) * GSTAGE_BYTES;
        CP_WAIT0();
        __syncthreads();

        if (t + 1 < T) {
            const unsigned snext = (unsigned)((t + 1) & 1) * GSTAGE_BYTES;
            const int k0 = (t + 1) * GBK;
#pragma unroll
            for (int i = 0; i < 4; i++) {
                int e = tid + i * 256;
                int r = e >> 3, kq = (e & 7) << 2;
                cp_async16(sA + snext + 4u * (r * GST + kq),
                           &A[(size_t)(m0 + r) * K + k0 + kq]);
                cp_async16(sB + snext + 4u * (r * GST + kq),
                           &B[(size_t)(n0 + r) * K + k0 + kq]);
            }
            CP_COMMIT();
        }

#pragma unroll
        for (int ks = 0; ks < GBK; ks += 8) {
            unsigned af[4][4], bf[2][4];
#pragma unroll
            for (int mt = 0; mt < 4; mt++) ldsm4(af[mt], aab[mt] + soff + ks * 4);
#pragma unroll
            for (int ntp = 0; ntp < 2; ntp++) ldsm4(bf[ntp], bbb[ntp] + soff + ks * 4);
#pragma unroll
            for (int mt = 0; mt < 4; mt++)
#pragma unroll
                for (int nt = 0; nt < 4; nt++)
                    mma_tf32(acc[mt][nt], af[mt], &bf[nt >> 1][(nt & 1) * 2]);
        }
        __syncthreads();
    }

#pragma unroll
    for (int mt = 0; mt < 4; mt++) {
#pragma unroll
        for (int nt = 0; nt < 4; nt++) {
            int r = m0 + wm + mt * 16 + lg;
            int c = n0 + wn + nt * 8 + (lt << 1);
            float b0 = bias ? bias[c] : 0.f;
            float b1 = bias ? bias[c + 1] : 0.f;
            float2 v0 = make_float2(acc[mt][nt][0] + b0, acc[mt][nt][1] + b1);
            float2 v1 = make_float2(acc[mt][nt][2] + b0, acc[mt][nt][3] + b1);
            *(float2*)&C[(size_t)r * N + c]       = v0;
            *(float2*)&C[(size_t)(r + 8) * N + c] = v1;
        }
    }
}

// ---------------------------------------------------------------------------
// RoPE cos/sin table
// ---------------------------------------------------------------------------
__global__ void rope_table()
{
    int idx = blockIdx.x * blockDim.x + threadIdx.x;  // over SEQ*32
    if (idx >= SEQ * 32) return;
    int i = idx & 31;
    int n = idx >> 5;
    float inv_freq = (float)pow(10000.0, -(double)i / 32.0);
    float phase = (float)n * inv_freq;
    g_cos[idx] = (float)cos((double)phase);
    g_sin[idx] = (float)sin((double)phase);
}

// ---------------------------------------------------------------------------
// RoPE + transpose: qkv [4096, 3072] -> Q,K (roped), V in [B,H,N,D],
// all values written tf32-rounded (attention consumes them directly).
// ---------------------------------------------------------------------------
__global__ void rope_transpose(const float* __restrict__ qkv,
                               float* __restrict__ Q, float* __restrict__ K,
                               float* __restrict__ V)
{
    int idx = blockIdx.x * blockDim.x + threadIdx.x;   // over B*H*N*D
    if (idx >= BATCH * HEADS * SEQ * HD) return;
    int d = idx & (HD - 1);
    int n = (idx >> 6) & (SEQ - 1);
    int h = (idx >> 17) & (HEADS - 1);
    int b = idx >> 21;

    const size_t mrow = (size_t)(b * SEQ + n) * (3 * C_DIM);
    const int col = h * HD + d;

    float qv = qkv[mrow + col];
    float kv = qkv[mrow + C_DIM + col];
    float vv = qkv[mrow + 2 * C_DIM + col];

    int i = d & 31;
    float c = g_cos[n * 32 + i];
    float s = g_sin[n * 32 + i];

    float qp = (d < 32) ? -qkv[mrow + col + 32] : qkv[mrow + col - 32];
    float kp = (d < 32) ? -qkv[mrow + C_DIM + col + 32] : qkv[mrow + C_DIM + col - 32];

    size_t o = ((size_t)(b * HEADS + h) * SEQ + n) * HD + d;
    Q[o] = f2tff(qv * c + qp * s);
    K[o] = f2tff(kv * c + kp * s);
    V[o] = f2tff(vv);
}

// ---------------------------------------------------------------------------
// Flash attention (R3-proven structure, tf32 mma, scalar fragment LDS):
//  - 128 Q rows/block, 8 warps; 64-row KV tiles
//  - softmax scale folded into Q at load (0.125 = 2^-3, exact on tf32 grid)
//  - K/V already tf32-rounded: raw uint4 smem fills
//  - P accumulator -> A-fragment via shfl (no smem round-trip)
//  - epilogue writes tf32-rounded output (out-proj consumes directly)
// ---------------------------------------------------------------------------
#define QTILE 128
#define KTILE 64
#define QKST  68
#define VST   72
#define ATTN_SMEM_BYTES ((QTILE*QKST + KTILE*QKST + KTILE*VST) * 4)

__global__ __launch_bounds__(256)
void attn_tf32(const float* __restrict__ Q, const float* __restrict__ K,
               const float* __restrict__ V, float* __restrict__ Out)
{
    extern __shared__ unsigned sm[];
    unsigned* Qs = sm;                       // [128][68] row=q, col=d
    unsigned* Ks = Qs + QTILE * QKST;        // [64][68]  row=kv, col=d
    unsigned* Vs = Ks + KTILE * QKST;        // [64][72]  row=kv, col=d

    const int tid  = threadIdx.x;
    const int lane = tid & 31;
    const int warp = tid >> 5;
    const int lg   = lane >> 2;
    const int lt   = lane & 3;
    const int b = blockIdx.z, h = blockIdx.y;
    const int q0 = blockIdx.x * QTILE;
    const int qr = warp * 16;                // warp's q-row base in tile

    const float* Qb = Q + (size_t)(b * HEADS + h) * SEQ * HD;
    const float* Kb = K + (size_t)(b * HEADS + h) * SEQ * HD;
    const float* Vb = V + (size_t)(b * HEADS + h) * SEQ * HD;

    // Load Q tile pre-scaled by 0.125 (exact, stays on tf32 grid)
#pragma unroll
    for (int i = 0; i < 8; i++) {
        int e = tid + i * 256;
        int r = e >> 4, c4 = (e & 15) << 2;
        float4 v = *(const float4*)&Qb[(size_t)(q0 + r) * HD + c4];
        *(uint4*)&Qs[r * QKST + c4] =
            make_uint4(f2tf(v.x * 0.125f), f2tf(v.y * 0.125f),
                       f2tf(v.z * 0.125f), f2tf(v.w * 0.125f));
    }

    float o[8][4];
#pragma unroll
    for (int nt = 0; nt < 8; nt++)
#pragma unroll
        for (int j = 0; j < 4; j++) o[nt][j] = 0.f;
    float m_lo = -1e30f, m_hi = -1e30f, l_lo = 0.f, l_hi = 0.f;

    __syncthreads();

    const int psrc = lg * 4 + (lt >> 1);     // shuffle source lane
    const bool podd = (lt & 1);

    for (int k0 = 0; k0 < SEQ; k0 += KTILE) {
        // K/V already tf32-rounded: raw copies
#pragma unroll
        for (int i = 0; i < 4; i++) {
            int e = tid + i * 256;
            int r = e >> 4, c4 = (e & 15) << 2;
            *(uint4*)&Ks[r * QKST + c4] =
                *(const uint4*)&Kb[(size_t)(k0 + r) * HD + c4];
            *(uint4*)&Vs[r * VST + c4] =
                *(const uint4*)&Vb[(size_t)(k0 + r) * HD + c4];
        }
        __syncthreads();

        // ---- S = Q K^T  (warp: 16 x 64) ----
        float s[8][4];
#pragma unroll
        for (int nt = 0; nt < 8; nt++)
#pragma unroll
            for (int j = 0; j < 4; j++) s[nt][j] = 0.f;

#pragma unroll
        for (int ks = 0; ks < 8; ks++) {
            unsigned af[4];
            int ar = (qr + lg) * QKST + ks * 8 + lt;
            af[0] = Qs[ar];
            af[1] = Qs[ar + 8 * QKST];
            af[2] = Qs[ar + 4];
            af[3] = Qs[ar + 8 * QKST + 4];
#pragma unroll
            for (int nt = 0; nt < 8; nt++) {
                unsigned bf[2];
                int br = (nt * 8 + lg) * QKST + ks * 8 + lt;
                bf[0] = Ks[br];
                bf[1] = Ks[br + 4];
                mma_tf32(s[nt], af, bf);
            }
        }

        // ---- online softmax on fragments (S pre-scaled via Q) ----
        float rmax_lo = -1e30f, rmax_hi = -1e30f;
#pragma unroll
        for (int nt = 0; nt < 8; nt++) {
            rmax_lo = fmaxf(rmax_lo, fmaxf(s[nt][0], s[nt][1]));
            rmax_hi = fmaxf(rmax_hi, fmaxf(s[nt][2], s[nt][3]));
        }
        rmax_lo = fmaxf(rmax_lo, __shfl_xor_sync(0xffffffffu, rmax_lo, 1));
        rmax_lo = fmaxf(rmax_lo, __shfl_xor_sync(0xffffffffu, rmax_lo, 2));
        rmax_hi = fmaxf(rmax_hi, __shfl_xor_sync(0xffffffffu, rmax_hi, 1));
        rmax_hi = fmaxf(rmax_hi, __shfl_xor_sync(0xffffffffu, rmax_hi, 2));

        float mn_lo = fmaxf(m_lo, rmax_lo);
        float mn_hi = fmaxf(m_hi, rmax_hi);
        float alpha_lo = __expf(m_lo - mn_lo);
        float alpha_hi = __expf(m_hi - mn_hi);
        m_lo = mn_lo; m_hi = mn_hi;

        float sum_lo = 0.f, sum_hi = 0.f;
#pragma unroll
        for (int nt = 0; nt < 8; nt++) {
            s[nt][0] = __expf(s[nt][0] - m_lo);
            s[nt][1] = __expf(s[nt][1] - m_lo);
            s[nt][2] = __expf(s[nt][2] - m_hi);
            s[nt][3] = __expf(s[nt][3] - m_hi);
            sum_lo += s[nt][0] + s[nt][1];
            sum_hi += s[nt][2] + s[nt][3];
            o[nt][0] *= alpha_lo; o[nt][1] *= alpha_lo;
            o[nt][2] *= alpha_hi; o[nt][3] *= alpha_hi;
        }
        sum_lo += __shfl_xor_sync(0xffffffffu, sum_lo, 1);
        sum_lo += __shfl_xor_sync(0xffffffffu, sum_lo, 2);
        sum_hi += __shfl_xor_sync(0xffffffffu, sum_hi, 1);
        sum_hi += __shfl_xor_sync(0xffffffffu, sum_hi, 2);
        l_lo = l_lo * alpha_lo + sum_lo;
        l_hi = l_hi * alpha_hi + sum_hi;

        // ---- O += P V : P accumulator -> A-fragment via shfl, no smem ----
#pragma unroll
        for (int ks = 0; ks < 8; ks++) {
            float e0  = __shfl_sync(0xffffffffu, s[ks][0], psrc);
            float q0v = __shfl_sync(0xffffffffu, s[ks][1], psrc);
            float e1  = __shfl_sync(0xffffffffu, s[ks][2], psrc);
            float q1v = __shfl_sync(0xffffffffu, s[ks][3], psrc);
            float e2  = __shfl_sync(0xffffffffu, s[ks][0], psrc + 2);
            float q2v = __shfl_sync(0xffffffffu, s[ks][1], psrc + 2);
            float e3  = __shfl_sync(0xffffffffu, s[ks][2], psrc + 2);
            float q3v = __shfl_sync(0xffffffffu, s[ks][3], psrc + 2);
            unsigned pf[4];
            pf[0] = f2tf(podd ? q0v : e0);
            pf[1] = f2tf(podd ? q1v : e1);
            pf[2] = f2tf(podd ? q2v : e2);
            pf[3] = f2tf(podd ? q3v : e3);
#pragma unroll
            for (int nt = 0; nt < 8; nt++) {
                unsigned vf[2];
                int vr = (ks * 8 + lt) * VST + nt * 8 + lg;
                vf[0] = Vs[vr];
                vf[1] = Vs[vr + 4 * VST];
                mma_tf32(o[nt], pf, vf);
            }
        }
        __syncthreads();
    }

    // ---- epilogue: normalize, tf32-round, write [B, N, H*D] ----
    float inv_lo = 1.0f / l_lo;
    float inv_hi = 1.0f / l_hi;
#pragma unroll
    for (int nt = 0; nt < 8; nt++) {
        int r = q0 + qr + lg;
        int c = h * HD + nt * 8 + (lt << 1);
        float2 v0 = make_float2(f2tff(o[nt][0] * inv_lo), f2tff(o[nt][1] * inv_lo));
        float2 v1 = make_float2(f2tff(o[nt][2] * inv_hi), f2tff(o[nt][3] * inv_hi));
        *(float2*)&Out[(size_t)(b * SEQ + r) * C_DIM + c]     = v0;
        *(float2*)&Out[(size_t)(b * SEQ + r + 8) * C_DIM + c] = v1;
    }
}

// ---------------------------------------------------------------------------
extern "C" void kernel_launch(void* const* d_in, const int* in_sizes, int n_in,
                              void* d_out, int out_size)
{
    const float* x    = (const float*)d_in[0];   // [2,2048,1024]
    const float* Wqkv = (const float*)d_in[1];   // [3072,1024]
    const float* Wout = (const float*)d_in[2];   // [1024,1024]
    const float* bout = (const float*)d_in[3];   // [1024]
    float* out = (float*)d_out;                  // [2,2048,1024]

    float *qkv, *Q, *K, *V, *attn, *xtf, *wqkv, *wout;
    cudaGetSymbolAddress((void**)&qkv,  g_qkv);
    cudaGetSymbolAddress((void**)&Q,    g_Q);
    cudaGetSymbolAddress((void**)&K,    g_K);
    cudaGetSymbolAddress((void**)&V,    g_V);
    cudaGetSymbolAddress((void**)&attn, g_attn);
    cudaGetSymbolAddress((void**)&xtf,  g_xtf);
    cudaGetSymbolAddress((void**)&wqkv, g_wqkv);
    cudaGetSymbolAddress((void**)&wout, g_wout);

    // 0) RoPE tables + tf32 pre-rounding of GEMM operands
    rope_table<<<(SEQ * 32 + 255) / 256, 256>>>();
    {
        int n4;
        n4 = M_ROWS * C_DIM / 4;
        round_tf32<<<(n4 + 255) / 256, 256>>>((const float4*)x, (float4*)xtf, n4);
        n4 = 3 * C_DIM * C_DIM / 4;
        round_tf32<<<(n4 + 255) / 256, 256>>>((const float4*)Wqkv, (float4*)wqkv, n4);
        n4 = C_DIM * C_DIM / 4;
        round_tf32<<<(n4 + 255) / 256, 256>>>((const float4*)Wout, (float4*)wout, n4);
    }

    cudaFuncSetAttribute(gemm_tf32_db,
                         cudaFuncAttributeMaxDynamicSharedMemorySize,
                         GEMM_SMEM_BYTES);

    // 1) QKV projection: [4096,3072] = xtf @ wqkv^T
    gemm_tf32_db<<<dim3(3 * C_DIM / GBN, M_ROWS / GBM), 256, GEMM_SMEM_BYTES>>>(
        xtf, wqkv, qkv, M_ROWS, 3 * C_DIM, C_DIM, nullptr);

    // 2) RoPE + transpose into [B,H,N,D] (tf32-rounded)
    {
        int total = BATCH * HEADS * SEQ * HD;
        rope_transpose<<<(total + 255) / 256, 256>>>(qkv, Q, K, V);
    }

    // 3) Flash attention -> [B,N,C] (tf32-rounded)
    cudaFuncSetAttribute(attn_tf32,
                         cudaFuncAttributeMaxDynamicSharedMemorySize,
                         ATTN_SMEM_BYTES);
    attn_tf32<<<dim3(SEQ / QTILE, HEADS, BATCH), 256, ATTN_SMEM_BYTES>>>(
        Q, K, V, attn);

    // 4) Output projection: out = attn @ wout^T + bout
    gemm_tf32_db<<<dim3(C_DIM / GBN, M_ROWS / GBM), 256, GEMM_SMEM_BYTES>>>(
        attn, wout, out, M_ROWS, C_DIM, C_DIM, bout);
}

// round 7
// speedup vs baseline: 1.4502x; 1.1910x over previous
#include <cuda_runtime.h>
#include <cuda_fp16.h>
#include <math.h>

// Problem constants
#define C_DIM   1024
#define HEADS   16
#define HD      64
#define BATCH   2
#define SEQ     2048
#define M_ROWS  (BATCH*SEQ)        // 4096

// Scratch (device globals: no allocation allowed)
__device__ float  g_qkv[(size_t)M_ROWS * 3 * C_DIM];          // [4096, 3072]
__device__ float  g_Q[(size_t)BATCH*HEADS*SEQ*HD];            // [B,H,N,D] tf32-rounded
__device__ float  g_K[(size_t)BATCH*HEADS*SEQ*HD];
__device__ __half g_Vh[(size_t)BATCH*HEADS*SEQ*HD];           // [B,H,N,D] fp16
__device__ float  g_attn[(size_t)M_ROWS * C_DIM];             // [B,N,H*D] tf32-rounded
__device__ float  g_xtf[(size_t)M_ROWS * C_DIM];              // x rounded to tf32
__device__ float  g_wqkv[(size_t)3 * C_DIM * C_DIM];          // Wqkv rounded
__device__ float  g_wout[(size_t)C_DIM * C_DIM];              // Wout rounded
__device__ float  g_cos[SEQ * 32];
__device__ float  g_sin[SEQ * 32];

// ---------------------------------------------------------------------------
// tf32 / fp16 / ldmatrix / cp.async helpers
// ---------------------------------------------------------------------------
__device__ __forceinline__ unsigned f2tf(float x) {
    unsigned r;
    asm("cvt.rna.tf32.f32 %0, %1;" : "=r"(r) : "f"(x));
    return r;
}
__device__ __forceinline__ float f2tff(float x) { return __uint_as_float(f2tf(x)); }

__device__ __forceinline__ unsigned pack_h2(float lo, float hi) {
    unsigned r;
    asm("cvt.rn.f16x2.f32 %0, %1, %2;" : "=r"(r) : "f"(hi), "f"(lo));
    return r;
}

__device__ __forceinline__ void mma_tf32(float* d, const unsigned* a, const unsigned* b) {
    asm volatile(
        "mma.sync.aligned.m16n8k8.row.col.f32.tf32.tf32.f32 "
        "{%0,%1,%2,%3}, {%4,%5,%6,%7}, {%8,%9}, {%0,%1,%2,%3};\n"
        : "+f"(d[0]), "+f"(d[1]), "+f"(d[2]), "+f"(d[3])
        : "r"(a[0]), "r"(a[1]), "r"(a[2]), "r"(a[3]), "r"(b[0]), "r"(b[1]));
}

__device__ __forceinline__ void mma_f16(float* d, const unsigned* a, unsigned b0, unsigned b1) {
    asm volatile(
        "mma.sync.aligned.m16n8k16.row.col.f32.f16.f16.f32 "
        "{%0,%1,%2,%3}, {%4,%5,%6,%7}, {%8,%9}, {%0,%1,%2,%3};\n"
        : "+f"(d[0]), "+f"(d[1]), "+f"(d[2]), "+f"(d[3])
        : "r"(a[0]), "r"(a[1]), "r"(a[2]), "r"(a[3]), "r"(b0), "r"(b1));
}

__device__ __forceinline__ void ldsm4(unsigned* r, unsigned addr) {
    asm volatile(
        "ldmatrix.sync.aligned.m8n8.x4.shared.b16 {%0,%1,%2,%3}, [%4];"
        : "=r"(r[0]), "=r"(r[1]), "=r"(r[2]), "=r"(r[3]) : "r"(addr));
}
__device__ __forceinline__ void ldsm4t(unsigned* r, unsigned addr) {
    asm volatile(
        "ldmatrix.sync.aligned.m8n8.x4.trans.shared.b16 {%0,%1,%2,%3}, [%4];"
        : "=r"(r[0]), "=r"(r[1]), "=r"(r[2]), "=r"(r[3]) : "r"(addr));
}

__device__ __forceinline__ void cp_async16(unsigned saddr, const void* gaddr) {
    asm volatile("cp.async.cg.shared.global [%0], [%1], 16;" :: "r"(saddr), "l"(gaddr));
}
#define CP_COMMIT() asm volatile("cp.async.commit_group;")
#define CP_WAIT0()  asm volatile("cp.async.wait_group 0;")

// ---------------------------------------------------------------------------
// Elementwise tf32 rounding
// ---------------------------------------------------------------------------
__global__ void round_tf32(const float4* __restrict__ in, float4* __restrict__ out, int n4)
{
    int i = blockIdx.x * blockDim.x + threadIdx.x;
    if (i < n4) {
        float4 v = in[i];
        out[i] = make_float4(f2tff(v.x), f2tff(v.y), f2tff(v.z), f2tff(v.w));
    }
}

// ---------------------------------------------------------------------------
// tf32 GEMM (NT), cp.async 2-stage double-buffered, ldmatrix fragments.
// Operands MUST already be tf32-rounded. C[M,N] = A[M,K]*B[N,K]^T (+bias)
// ---------------------------------------------------------------------------
#define GBM 128
#define GBN 128
#define GBK 32
#define GST 36
#define GSTAGE_BYTES ((GBM + GBN) * GST * 4)
#define GEMM_SMEM_BYTES (2 * GSTAGE_BYTES)   // 73728

__global__ __launch_bounds__(256, 2)
void gemm_tf32_db(const float* __restrict__ A, const float* __restrict__ B,
                  float* __restrict__ C, int M, int N, int K,
                  const float* __restrict__ bias)
{
    extern __shared__ unsigned gsm[];

    const int tid  = threadIdx.x;
    const int lane = tid & 31;
    const int warp = tid >> 5;
    const int wm   = (warp >> 2) * 64;
    const int wn   = (warp & 3) * 32;
    const int m0   = blockIdx.y * GBM;
    const int n0   = blockIdx.x * GBN;
    const int lg   = lane >> 2;
    const int lt   = lane & 3;
    const int t8   = lane >> 3;
    const int rr   = lane & 7;

    const unsigned sA = (unsigned)__cvta_generic_to_shared(gsm);
    const unsigned sB = sA + GBM * GST * 4;

    unsigned aab[4];
#pragma unroll
    for (int mt = 0; mt < 4; mt++)
        aab[mt] = sA + 4u * ((wm + mt * 16 + (t8 & 1) * 8 + rr) * GST + (t8 >> 1) * 4);
    unsigned bbb[2];
#pragma unroll
    for (int ntp = 0; ntp < 2; ntp++)
        bbb[ntp] = sB + 4u * ((wn + (ntp * 2 + (t8 >> 1)) * 8 + rr) * GST + (t8 & 1) * 4);

    float acc[4][4][4];
#pragma unroll
    for (int mt = 0; mt < 4; mt++)
#pragma unroll
        for (int nt = 0; nt < 4; nt++)
#pragma unroll
            for (int j = 0; j < 4; j++) acc[mt][nt][j] = 0.f;

    const int T = K / GBK;

    {
#pragma unroll
        for (int i = 0; i < 4; i++) {
            int e = tid + i * 256;
            int r = e >> 3, kq = (e & 7) << 2;
            cp_async16(sA + 4u * (r * GST + kq), &A[(size_t)(m0 + r) * K + kq]);
            cp_async16(sB + 4u * (r * GST + kq), &B[(size_t)(n0 + r) * K + kq]);
        }
        CP_COMMIT();
    }

    for (int t = 0; t < T; t++) {
        const unsigned soff = (unsigned)(t & 1) * GSTAGE_BYTES;
        CP_WAIT0();
        __syncthreads();

        if (t + 1 < T) {
            const unsigned snext = (unsigned)((t + 1) & 1) * GSTAGE_BYTES;
            const int k0 = (t + 1) * GBK;
#pragma unroll
            for (int i = 0; i < 4; i++) {
                int e = tid + i * 256;
                int r = e >> 3, kq = (e & 7) << 2;
                cp_async16(sA + snext + 4u * (r * GST + kq),
                           &A[(size_t)(m0 + r) * K + k0 + kq]);
                cp_async16(sB + snext + 4u * (r * GST + kq),
                           &B[(size_t)(n0 + r) * K + k0 + kq]);
            }
            CP_COMMIT();
        }

#pragma unroll
        for (int ks = 0; ks < GBK; ks += 8) {
            unsigned af[4][4], bf[2][4];
#pragma unroll
            for (int mt = 0; mt < 4; mt++) ldsm4(af[mt], aab[mt] + soff + ks * 4);
#pragma unroll
            for (int ntp = 0; ntp < 2; ntp++) ldsm4(bf[ntp], bbb[ntp] + soff + ks * 4);
#pragma unroll
            for (int mt = 0; mt < 4; mt++)
#pragma unroll
                for (int nt = 0; nt < 4; nt++)
                    mma_tf32(acc[mt][nt], af[mt], &bf[nt >> 1][(nt & 1) * 2]);
        }
        __syncthreads();
    }

#pragma unroll
    for (int mt = 0; mt < 4; mt++) {
#pragma unroll
        for (int nt = 0; nt < 4; nt++) {
            int r = m0 + wm + mt * 16 + lg;
            int c = n0 + wn + nt * 8 + (lt << 1);
            float b0 = bias ? bias[c] : 0.f;
            float b1 = bias ? bias[c + 1] : 0.f;
            float2 v0 = make_float2(acc[mt][nt][0] + b0, acc[mt][nt][1] + b1);
            float2 v1 = make_float2(acc[mt][nt][2] + b0, acc[mt][nt][3] + b1);
            *(float2*)&C[(size_t)r * N + c]       = v0;
            *(float2*)&C[(size_t)(r + 8) * N + c] = v1;
        }
    }
}

// ---------------------------------------------------------------------------
// RoPE cos/sin table
// ---------------------------------------------------------------------------
__global__ void rope_table()
{
    int idx = blockIdx.x * blockDim.x + threadIdx.x;
    if (idx >= SEQ * 32) return;
    int i = idx & 31;
    int n = idx >> 5;
    float inv_freq = (float)pow(10000.0, -(double)i / 32.0);
    float phase = (float)n * inv_freq;
    g_cos[idx] = (float)cos((double)phase);
    g_sin[idx] = (float)sin((double)phase);
}

// ---------------------------------------------------------------------------
// RoPE + transpose: qkv -> Q,K (roped, tf32-rounded), V (fp16) in [B,H,N,D]
// ---------------------------------------------------------------------------
__global__ void rope_transpose(const float* __restrict__ qkv,
                               float* __restrict__ Q, float* __restrict__ K,
                               __half* __restrict__ V)
{
    int idx = blockIdx.x * blockDim.x + threadIdx.x;
    if (idx >= BATCH * HEADS * SEQ * HD) return;
    int d = idx & (HD - 1);
    int n = (idx >> 6) & (SEQ - 1);
    int h = (idx >> 17) & (HEADS - 1);
    int b = idx >> 21;

    const size_t mrow = (size_t)(b * SEQ + n) * (3 * C_DIM);
    const int col = h * HD + d;

    float qv = qkv[mrow + col];
    float kv = qkv[mrow + C_DIM + col];
    float vv = qkv[mrow + 2 * C_DIM + col];

    int i = d & 31;
    float c = g_cos[n * 32 + i];
    float s = g_sin[n * 32 + i];

    float qp = (d < 32) ? -qkv[mrow + col + 32] : qkv[mrow + col - 32];
    float kp = (d < 32) ? -qkv[mrow + C_DIM + col + 32] : qkv[mrow + C_DIM + col - 32];

    size_t o = ((size_t)(b * HEADS + h) * SEQ + n) * HD + d;
    Q[o] = f2tff(qv * c + qp * s);
    K[o] = f2tff(kv * c + kp * s);
    V[o] = __float2half(vv);
}

// ---------------------------------------------------------------------------
// Flash attention v5:
//  - S = QK^T in tf32 (scalar-LDS fragments, proven)
//  - P*V in fp16 m16n8k16: accumulator == A-fragment (zero shuffles),
//    V fragments via ldmatrix.x4.trans from natural [k][d] fp16 smem
//  - 128 Q rows/block, 8 warps; 64-row KV tiles; scale folded into Q
// ---------------------------------------------------------------------------
#define QTILE 128
#define KTILE 64
#define QKST  68
#define VSTH  72   // halves per V row: 144B, 16B-aligned, ldmatrix conflict-free
#define ATTN_SMEM_BYTES ((QTILE*QKST + KTILE*QKST) * 4 + KTILE*VSTH*2)

__global__ __launch_bounds__(256)
void attn_tf32(const float* __restrict__ Q, const float* __restrict__ K,
               const __half* __restrict__ V, float* __restrict__ Out)
{
    extern __shared__ unsigned sm[];
    unsigned* Qs = sm;                       // [128][68] row=q, col=d (tf32)
    unsigned* Ks = Qs + QTILE * QKST;        // [64][68]  row=kv, col=d (tf32)
    __half*   Vs = (__half*)(Ks + KTILE * QKST);   // [64][72] row=kv, col=d (fp16)

    const int tid  = threadIdx.x;
    const int lane = tid & 31;
    const int warp = tid >> 5;
    const int lg   = lane >> 2;
    const int lt   = lane & 3;
    const int b = blockIdx.z, h = blockIdx.y;
    const int q0 = blockIdx.x * QTILE;
    const int qr = warp * 16;

    const unsigned sbase = (unsigned)__cvta_generic_to_shared(sm);
    const unsigned sV = sbase + 4u * (QTILE * QKST + KTILE * QKST);

    const float*  Qb = Q + (size_t)(b * HEADS + h) * SEQ * HD;
    const float*  Kb = K + (size_t)(b * HEADS + h) * SEQ * HD;
    const __half* Vb = V + (size_t)(b * HEADS + h) * SEQ * HD;

    // ldmatrix.trans per-lane base address into V tile:
    // lane = 8m + r; matrix m covers k-offset 8*(m&1), d-offset 8*(m>>1)
    const int lm_m = lane >> 3, lm_r = lane & 7;
    const unsigned vab = sV + 2u * ((8 * (lm_m & 1) + lm_r) * VSTH + 8 * (lm_m >> 1));

    // Load Q tile pre-scaled by 0.125 (exact)
#pragma unroll
    for (int i = 0; i < 8; i++) {
        int e = tid + i * 256;
        int r = e >> 4, c4 = (e & 15) << 2;
        float4 v = *(const float4*)&Qb[(size_t)(q0 + r) * HD + c4];
        *(uint4*)&Qs[r * QKST + c4] =
            make_uint4(f2tf(v.x * 0.125f), f2tf(v.y * 0.125f),
                       f2tf(v.z * 0.125f), f2tf(v.w * 0.125f));
    }

    float o[8][4];
#pragma unroll
    for (int nt = 0; nt < 8; nt++)
#pragma unroll
        for (int j = 0; j < 4; j++) o[nt][j] = 0.f;
    float m_lo = -1e30f, m_hi = -1e30f, l_lo = 0.f, l_hi = 0.f;

    __syncthreads();

    for (int k0 = 0; k0 < SEQ; k0 += KTILE) {
        // K (tf32, raw uint4) and V (fp16, raw uint4 = 8 halves)
#pragma unroll
        for (int i = 0; i < 4; i++) {
            int e = tid + i * 256;
            int r = e >> 4, c4 = (e & 15) << 2;
            *(uint4*)&Ks[r * QKST + c4] =
                *(const uint4*)&Kb[(size_t)(k0 + r) * HD + c4];
        }
#pragma unroll
        for (int i = 0; i < 2; i++) {
            int e = tid + i * 256;
            int r = e >> 3, c8 = (e & 7) << 3;
            *(uint4*)&Vs[r * VSTH + c8] =
                *(const uint4*)&Vb[(size_t)(k0 + r) * HD + c8];
        }
        __syncthreads();

        // ---- S = Q K^T  (warp: 16 x 64, tf32) ----
        float s[8][4];
#pragma unroll
        for (int nt = 0; nt < 8; nt++)
#pragma unroll
            for (int j = 0; j < 4; j++) s[nt][j] = 0.f;

#pragma unroll
        for (int ks = 0; ks < 8; ks++) {
            unsigned af[4];
            int ar = (qr + lg) * QKST + ks * 8 + lt;
            af[0] = Qs[ar];
            af[1] = Qs[ar + 8 * QKST];
            af[2] = Qs[ar + 4];
            af[3] = Qs[ar + 8 * QKST + 4];
#pragma unroll
            for (int nt = 0; nt < 8; nt++) {
                unsigned bf[2];
                int br = (nt * 8 + lg) * QKST + ks * 8 + lt;
                bf[0] = Ks[br];
                bf[1] = Ks[br + 4];
                mma_tf32(s[nt], af, bf);
            }
        }

        // ---- online softmax on fragments ----
        float rmax_lo = -1e30f, rmax_hi = -1e30f;
#pragma unroll
        for (int nt = 0; nt < 8; nt++) {
            rmax_lo = fmaxf(rmax_lo, fmaxf(s[nt][0], s[nt][1]));
            rmax_hi = fmaxf(rmax_hi, fmaxf(s[nt][2], s[nt][3]));
        }
        rmax_lo = fmaxf(rmax_lo, __shfl_xor_sync(0xffffffffu, rmax_lo, 1));
        rmax_lo = fmaxf(rmax_lo, __shfl_xor_sync(0xffffffffu, rmax_lo, 2));
        rmax_hi = fmaxf(rmax_hi, __shfl_xor_sync(0xffffffffu, rmax_hi, 1));
        rmax_hi = fmaxf(rmax_hi, __shfl_xor_sync(0xffffffffu, rmax_hi, 2));

        float mn_lo = fmaxf(m_lo, rmax_lo);
        float mn_hi = fmaxf(m_hi, rmax_hi);
        float alpha_lo = __expf(m_lo - mn_lo);
        float alpha_hi = __expf(m_hi - mn_hi);
        m_lo = mn_lo; m_hi = mn_hi;

        float sum_lo = 0.f, sum_hi = 0.f;
#pragma unroll
        for (int nt = 0; nt < 8; nt++) {
            s[nt][0] = __expf(s[nt][0] - m_lo);
            s[nt][1] = __expf(s[nt][1] - m_lo);
            s[nt][2] = __expf(s[nt][2] - m_hi);
            s[nt][3] = __expf(s[nt][3] - m_hi);
            sum_lo += s[nt][0] + s[nt][1];
            sum_hi += s[nt][2] + s[nt][3];
            o[nt][0] *= alpha_lo; o[nt][1] *= alpha_lo;
            o[nt][2] *= alpha_hi; o[nt][3] *= alpha_hi;
        }
        sum_lo += __shfl_xor_sync(0xffffffffu, sum_lo, 1);
        sum_lo += __shfl_xor_sync(0xffffffffu, sum_lo, 2);
        sum_hi += __shfl_xor_sync(0xffffffffu, sum_hi, 1);
        sum_hi += __shfl_xor_sync(0xffffffffu, sum_hi, 2);
        l_lo = l_lo * alpha_lo + sum_lo;
        l_hi = l_hi * alpha_hi + sum_hi;

        // ---- O += P V  (fp16 m16n8k16; P acc == A-frag, V via ldmatrix.trans) ----
#pragma unroll
        for (int ks = 0; ks < 4; ks++) {
            unsigned af[4];
            af[0] = pack_h2(s[2 * ks][0],     s[2 * ks][1]);
            af[1] = pack_h2(s[2 * ks][2],     s[2 * ks][3]);
            af[2] = pack_h2(s[2 * ks + 1][0], s[2 * ks + 1][1]);
            af[3] = pack_h2(s[2 * ks + 1][2], s[2 * ks + 1][3]);
#pragma unroll
            for (int dtp = 0; dtp < 4; dtp++) {
                unsigned vf[4];
                ldsm4t(vf, vab + (unsigned)(ks * 16 * VSTH * 2) + (unsigned)(dtp * 32));
                mma_f16(o[2 * dtp],     af, vf[0], vf[1]);
                mma_f16(o[2 * dtp + 1], af, vf[2], vf[3]);
            }
        }
        __syncthreads();
    }

    // ---- epilogue: normalize, tf32-round, write [B, N, H*D] ----
    float inv_lo = 1.0f / l_lo;
    float inv_hi = 1.0f / l_hi;
#pragma unroll
    for (int nt = 0; nt < 8; nt++) {
        int r = q0 + qr + lg;
        int c = h * HD + nt * 8 + (lt << 1);
        float2 v0 = make_float2(f2tff(o[nt][0] * inv_lo), f2tff(o[nt][1] * inv_lo));
        float2 v1 = make_float2(f2tff(o[nt][2] * inv_hi), f2tff(o[nt][3] * inv_hi));
        *(float2*)&Out[(size_t)(b * SEQ + r) * C_DIM + c]     = v0;
        *(float2*)&Out[(size_t)(b * SEQ + r + 8) * C_DIM + c] = v1;
    }
}

// ---------------------------------------------------------------------------
extern "C" void kernel_launch(void* const* d_in, const int* in_sizes, int n_in,
                              void* d_out, int out_size)
{
    const float* x    = (const float*)d_in[0];
    const float* Wqkv = (const float*)d_in[1];
    const float* Wout = (const float*)d_in[2];
    const float* bout = (const float*)d_in[3];
    float* out = (float*)d_out;

    float *qkv, *Q, *K, *attn, *xtf, *wqkv, *wout;
    __half* Vh;
    cudaGetSymbolAddress((void**)&qkv,  g_qkv);
    cudaGetSymbolAddress((void**)&Q,    g_Q);
    cudaGetSymbolAddress((void**)&K,    g_K);
    cudaGetSymbolAddress((void**)&Vh,   g_Vh);
    cudaGetSymbolAddress((void**)&attn, g_attn);
    cudaGetSymbolAddress((void**)&xtf,  g_xtf);
    cudaGetSymbolAddress((void**)&wqkv, g_wqkv);
    cudaGetSymbolAddress((void**)&wout, g_wout);

    // 0) RoPE tables + tf32 pre-rounding of GEMM operands
    rope_table<<<(SEQ * 32 + 255) / 256, 256>>>();
    {
        int n4;
        n4 = M_ROWS * C_DIM / 4;
        round_tf32<<<(n4 + 255) / 256, 256>>>((const float4*)x, (float4*)xtf, n4);
        n4 = 3 * C_DIM * C_DIM / 4;
        round_tf32<<<(n4 + 255) / 256, 256>>>((const float4*)Wqkv, (float4*)wqkv, n4);
        n4 = C_DIM * C_DIM / 4;
        round_tf32<<<(n4 + 255) / 256, 256>>>((const float4*)Wout, (float4*)wout, n4);
    }

    cudaFuncSetAttribute(gemm_tf32_db,
                         cudaFuncAttributeMaxDynamicSharedMemorySize,
                         GEMM_SMEM_BYTES);

    // 1) QKV projection
    gemm_tf32_db<<<dim3(3 * C_DIM / GBN, M_ROWS / GBM), 256, GEMM_SMEM_BYTES>>>(
        xtf, wqkv, qkv, M_ROWS, 3 * C_DIM, C_DIM, nullptr);

    // 2) RoPE + transpose
    {
        int total = BATCH * HEADS * SEQ * HD;
        rope_transpose<<<(total + 255) / 256, 256>>>(qkv, Q, K, Vh);
    }

    // 3) Flash attention v5 (tf32 S, fp16 PV)
    cudaFuncSetAttribute(attn_tf32,
                         cudaFuncAttributeMaxDynamicSharedMemorySize,
                         ATTN_SMEM_BYTES);
    attn_tf32<<<dim3(SEQ / QTILE, HEADS, BATCH), 256, ATTN_SMEM_BYTES>>>(
        Q, K, Vh, attn);

    // 4) Output projection
    gemm_tf32_db<<<dim3(C_DIM / GBN, M_ROWS / GBM), 256, GEMM_SMEM_BYTES>>>(
        attn, wout, out, M_ROWS, C_DIM, C_DIM, bout);
}

// round 8
// speedup vs baseline: 1.7021x; 1.1737x over previous
#include <cuda_runtime.h>
#include <cuda_fp16.h>
#include <math.h>

// Problem constants
#define C_DIM   1024
#define HEADS   16
#define HD      64
#define BATCH   2
#define SEQ     2048
#define M_ROWS  (BATCH*SEQ)        // 4096

// Scratch (device globals: no allocation allowed)
__device__ float  g_qkv[(size_t)M_ROWS * 3 * C_DIM];          // [4096, 3072]
__device__ __half g_Qh[(size_t)BATCH*HEADS*SEQ*HD];           // [B,H,N,D] fp16, pre-scaled
__device__ __half g_Kh[(size_t)BATCH*HEADS*SEQ*HD];           // fp16
__device__ __half g_Vh[(size_t)BATCH*HEADS*SEQ*HD];           // fp16
__device__ float  g_attn[(size_t)M_ROWS * C_DIM];             // [B,N,H*D] tf32-rounded
__device__ float  g_xtf[(size_t)M_ROWS * C_DIM];              // x rounded to tf32
__device__ float  g_wqkv[(size_t)3 * C_DIM * C_DIM];          // Wqkv rounded
__device__ float  g_wout[(size_t)C_DIM * C_DIM];              // Wout rounded
__device__ float  g_cos[SEQ * 32];
__device__ float  g_sin[SEQ * 32];

// ---------------------------------------------------------------------------
// helpers
// ---------------------------------------------------------------------------
__device__ __forceinline__ unsigned f2tf(float x) {
    unsigned r;
    asm("cvt.rna.tf32.f32 %0, %1;" : "=r"(r) : "f"(x));
    return r;
}
__device__ __forceinline__ float f2tff(float x) { return __uint_as_float(f2tf(x)); }

__device__ __forceinline__ unsigned pack_h2(float lo, float hi) {
    unsigned r;
    asm("cvt.rn.f16x2.f32 %0, %1, %2;" : "=r"(r) : "f"(hi), "f"(lo));
    return r;
}

__device__ __forceinline__ void mma_tf32(float* d, const unsigned* a, const unsigned* b) {
    asm volatile(
        "mma.sync.aligned.m16n8k8.row.col.f32.tf32.tf32.f32 "
        "{%0,%1,%2,%3}, {%4,%5,%6,%7}, {%8,%9}, {%0,%1,%2,%3};\n"
        : "+f"(d[0]), "+f"(d[1]), "+f"(d[2]), "+f"(d[3])
        : "r"(a[0]), "r"(a[1]), "r"(a[2]), "r"(a[3]), "r"(b[0]), "r"(b[1]));
}

__device__ __forceinline__ void mma_f16(float* d, const unsigned* a, unsigned b0, unsigned b1) {
    asm volatile(
        "mma.sync.aligned.m16n8k16.row.col.f32.f16.f16.f32 "
        "{%0,%1,%2,%3}, {%4,%5,%6,%7}, {%8,%9}, {%0,%1,%2,%3};\n"
        : "+f"(d[0]), "+f"(d[1]), "+f"(d[2]), "+f"(d[3])
        : "r"(a[0]), "r"(a[1]), "r"(a[2]), "r"(a[3]), "r"(b0), "r"(b1));
}

__device__ __forceinline__ void ldsm4(unsigned* r, unsigned addr) {
    asm volatile(
        "ldmatrix.sync.aligned.m8n8.x4.shared.b16 {%0,%1,%2,%3}, [%4];"
        : "=r"(r[0]), "=r"(r[1]), "=r"(r[2]), "=r"(r[3]) : "r"(addr));
}
__device__ __forceinline__ void ldsm4t(unsigned* r, unsigned addr) {
    asm volatile(
        "ldmatrix.sync.aligned.m8n8.x4.trans.shared.b16 {%0,%1,%2,%3}, [%4];"
        : "=r"(r[0]), "=r"(r[1]), "=r"(r[2]), "=r"(r[3]) : "r"(addr));
}

__device__ __forceinline__ void cp_async16(unsigned saddr, const void* gaddr) {
    asm volatile("cp.async.cg.shared.global [%0], [%1], 16;" :: "r"(saddr), "l"(gaddr));
}
#define CP_COMMIT() asm volatile("cp.async.commit_group;")
#define CP_WAIT0()  asm volatile("cp.async.wait_group 0;")

// ---------------------------------------------------------------------------
// Elementwise tf32 rounding
// ---------------------------------------------------------------------------
__global__ void round_tf32(const float4* __restrict__ in, float4* __restrict__ out, int n4)
{
    int i = blockIdx.x * blockDim.x + threadIdx.x;
    if (i < n4) {
        float4 v = in[i];
        out[i] = make_float4(f2tff(v.x), f2tff(v.y), f2tff(v.z), f2tff(v.w));
    }
}

// ---------------------------------------------------------------------------
// tf32 GEMM (NT), cp.async 2-stage double-buffered, ldmatrix fragments.
// ---------------------------------------------------------------------------
#define GBM 128
#define GBN 128
#define GBK 32
#define GST 36
#define GSTAGE_BYTES ((GBM + GBN) * GST * 4)
#define GEMM_SMEM_BYTES (2 * GSTAGE_BYTES)   // 73728

__global__ __launch_bounds__(256, 2)
void gemm_tf32_db(const float* __restrict__ A, const float* __restrict__ B,
                  float* __restrict__ C, int M, int N, int K,
                  const float* __restrict__ bias)
{
    extern __shared__ unsigned gsm[];

    const int tid  = threadIdx.x;
    const int lane = tid & 31;
    const int warp = tid >> 5;
    const int wm   = (warp >> 2) * 64;
    const int wn   = (warp & 3) * 32;
    const int m0   = blockIdx.y * GBM;
    const int n0   = blockIdx.x * GBN;
    const int lg   = lane >> 2;
    const int lt   = lane & 3;
    const int t8   = lane >> 3;
    const int rr   = lane & 7;

    const unsigned sA = (unsigned)__cvta_generic_to_shared(gsm);
    const unsigned sB = sA + GBM * GST * 4;

    unsigned aab[4];
#pragma unroll
    for (int mt = 0; mt < 4; mt++)
        aab[mt] = sA + 4u * ((wm + mt * 16 + (t8 & 1) * 8 + rr) * GST + (t8 >> 1) * 4);
    unsigned bbb[2];
#pragma unroll
    for (int ntp = 0; ntp < 2; ntp++)
        bbb[ntp] = sB + 4u * ((wn + (ntp * 2 + (t8 >> 1)) * 8 + rr) * GST + (t8 & 1) * 4);

    float acc[4][4][4];
#pragma unroll
    for (int mt = 0; mt < 4; mt++)
#pragma unroll
        for (int nt = 0; nt < 4; nt++)
#pragma unroll
            for (int j = 0; j < 4; j++) acc[mt][nt][j] = 0.f;

    const int T = K / GBK;

    {
#pragma unroll
        for (int i = 0; i < 4; i++) {
            int e = tid + i * 256;
            int r = e >> 3, kq = (e & 7) << 2;
            cp_async16(sA + 4u * (r * GST + kq), &A[(size_t)(m0 + r) * K + kq]);
            cp_async16(sB + 4u * (r * GST + kq), &B[(size_t)(n0 + r) * K + kq]);
        }
        CP_COMMIT();
    }

    for (int t = 0; t < T; t++) {
        const unsigned soff = (unsigned)(t & 1) * GSTAGE_BYTES;
        CP_WAIT0();
        __syncthreads();

        if (t + 1 < T) {
            const unsigned snext = (unsigned)((t + 1) & 1) * GSTAGE_BYTES;
            const int k0 = (t + 1) * GBK;
#pragma unroll
            for (int i = 0; i < 4; i++) {
                int e = tid + i * 256;
                int r = e >> 3, kq = (e & 7) << 2;
                cp_async16(sA + snext + 4u * (r * GST + kq),
                           &A[(size_t)(m0 + r) * K + k0 + kq]);
                cp_async16(sB + snext + 4u * (r * GST + kq),
                           &B[(size_t)(n0 + r) * K + k0 + kq]);
            }
            CP_COMMIT();
        }

#pragma unroll
        for (int ks = 0; ks < GBK; ks += 8) {
            unsigned af[4][4], bf[2][4];
#pragma unroll
            for (int mt = 0; mt < 4; mt++) ldsm4(af[mt], aab[mt] + soff + ks * 4);
#pragma unroll
            for (int ntp = 0; ntp < 2; ntp++) ldsm4(bf[ntp], bbb[ntp] + soff + ks * 4);
#pragma unroll
            for (int mt = 0; mt < 4; mt++)
#pragma unroll
                for (int nt = 0; nt < 4; nt++)
                    mma_tf32(acc[mt][nt], af[mt], &bf[nt >> 1][(nt & 1) * 2]);
        }
        __syncthreads();
    }

#pragma unroll
    for (int mt = 0; mt < 4; mt++) {
#pragma unroll
        for (int nt = 0; nt < 4; nt++) {
            int r = m0 + wm + mt * 16 + lg;
            int c = n0 + wn + nt * 8 + (lt << 1);
            float b0 = bias ? bias[c] : 0.f;
            float b1 = bias ? bias[c + 1] : 0.f;
            float2 v0 = make_float2(acc[mt][nt][0] + b0, acc[mt][nt][1] + b1);
            float2 v1 = make_float2(acc[mt][nt][2] + b0, acc[mt][nt][3] + b1);
            *(float2*)&C[(size_t)r * N + c]       = v0;
            *(float2*)&C[(size_t)(r + 8) * N + c] = v1;
        }
    }
}

// ---------------------------------------------------------------------------
// RoPE cos/sin table
// ---------------------------------------------------------------------------
__global__ void rope_table()
{
    int idx = blockIdx.x * blockDim.x + threadIdx.x;
    if (idx >= SEQ * 32) return;
    int i = idx & 31;
    int n = idx >> 5;
    float inv_freq = (float)pow(10000.0, -(double)i / 32.0);
    float phase = (float)n * inv_freq;
    g_cos[idx] = (float)cos((double)phase);
    g_sin[idx] = (float)sin((double)phase);
}

// ---------------------------------------------------------------------------
// RoPE + transpose: qkv -> Q (fp16, pre-scaled by 0.125), K (fp16), V (fp16)
// in [B,H,N,D]
// ---------------------------------------------------------------------------
__global__ void rope_transpose(const float* __restrict__ qkv,
                               __half* __restrict__ Q, __half* __restrict__ K,
                               __half* __restrict__ V)
{
    int idx = blockIdx.x * blockDim.x + threadIdx.x;
    if (idx >= BATCH * HEADS * SEQ * HD) return;
    int d = idx & (HD - 1);
    int n = (idx >> 6) & (SEQ - 1);
    int h = (idx >> 17) & (HEADS - 1);
    int b = idx >> 21;

    const size_t mrow = (size_t)(b * SEQ + n) * (3 * C_DIM);
    const int col = h * HD + d;

    float qv = qkv[mrow + col];
    float kv = qkv[mrow + C_DIM + col];
    float vv = qkv[mrow + 2 * C_DIM + col];

    int i = d & 31;
    float c = g_cos[n * 32 + i];
    float s = g_sin[n * 32 + i];

    float qp = (d < 32) ? -qkv[mrow + col + 32] : qkv[mrow + col - 32];
    float kp = (d < 32) ? -qkv[mrow + C_DIM + col + 32] : qkv[mrow + C_DIM + col - 32];

    size_t o = ((size_t)(b * HEADS + h) * SEQ + n) * HD + d;
    Q[o] = __float2half((qv * c + qp * s) * 0.125f);   // scale exact (2^-3)
    K[o] = __float2half(kv * c + kp * s);
    V[o] = __float2half(vv);
}

// ---------------------------------------------------------------------------
// Flash attention v6 — full fp16 mma (m16n8k16), fp32 accum/softmax:
//  - 128 Q rows/block, 8 warps; 64-row KV tiles, cp.async double-buffered
//  - Q/K/V fp16 in smem, stride 72 halves (144B rows, conflict-free ldmatrix)
//  - S via ldsm4 (Q row-major A, K row-major B), PV: acc==A-frag + ldsm4t V
// ---------------------------------------------------------------------------
#define QTILE 128
#define KTILE 64
#define STH   72                                // halves per row
#define Q_BYTES   (QTILE * STH * 2)             // 18432
#define KV_STAGE  (2 * KTILE * STH * 2)         // K+V per stage = 18432
#define ATTN_SMEM_BYTES (Q_BYTES + 2 * KV_STAGE)  // 55296

__global__ __launch_bounds__(256)
void attn_f16(const __half* __restrict__ Q, const __half* __restrict__ K,
              const __half* __restrict__ V, float* __restrict__ Out)
{
    extern __shared__ __half hsm[];

    const int tid  = threadIdx.x;
    const int lane = tid & 31;
    const int warp = tid >> 5;
    const int lg   = lane >> 2;
    const int lt   = lane & 3;
    const int t8   = lane >> 3;
    const int rr   = lane & 7;
    const int b = blockIdx.z, h = blockIdx.y;
    const int q0 = blockIdx.x * QTILE;
    const int qr = warp * 16;

    const unsigned sQ  = (unsigned)__cvta_generic_to_shared(hsm);
    const unsigned sKV = sQ + Q_BYTES;

    const __half* Qb = Q + (size_t)(b * HEADS + h) * SEQ * HD;
    const __half* Kb = K + (size_t)(b * HEADS + h) * SEQ * HD;
    const __half* Vb = V + (size_t)(b * HEADS + h) * SEQ * HD;

    // per-lane ldmatrix bases
    // A(Q): m0 rows0-7/k0-7, m1 rows8-15/k0-7, m2 rows0-7/k8-15, m3 rows8-15/k8-15
    const unsigned aQ = sQ + 2u * ((qr + (t8 & 1) * 8 + rr) * STH + (t8 >> 1) * 8);
    // B(K): covers 2 n-tiles: m0/m1 = n-rows 0-7 (k0-7,k8-15), m2/m3 = n-rows 8-15
    const unsigned kOff = 2u * (((t8 >> 1) * 8 + rr) * STH + (t8 & 1) * 8);
    // V (trans): m covers k-offset 8*(m&1), d-offset 8*(m>>1)
    const unsigned vOff = 2u * ((8 * (t8 & 1) + rr) * STH + 8 * (t8 >> 1));

    // Load Q tile (raw uint4 copies; already fp16 + pre-scaled)
#pragma unroll
    for (int i = 0; i < 4; i++) {
        int e = tid + i * 256;
        int r = e >> 3, c8 = (e & 7) << 3;
        *(uint4*)&hsm[r * STH + c8] = *(const uint4*)&Qb[(size_t)(q0 + r) * HD + c8];
    }

    // Prefetch KV tile 0 into stage 0
    {
        const unsigned st = sKV;
#pragma unroll
        for (int i = 0; i < 2; i++) {
            int e = tid + i * 256;
            int r = e >> 3, c8 = (e & 7) << 3;
            cp_async16(st + 2u * (r * STH + c8), &Kb[(size_t)r * HD + c8]);
            cp_async16(st + (unsigned)(KTILE * STH * 2) + 2u * (r * STH + c8),
                       &Vb[(size_t)r * HD + c8]);
        }
        CP_COMMIT();
    }

    float o[8][4];
#pragma unroll
    for (int nt = 0; nt < 8; nt++)
#pragma unroll
        for (int j = 0; j < 4; j++) o[nt][j] = 0.f;
    float m_lo = -1e30f, m_hi = -1e30f, l_lo = 0.f, l_hi = 0.f;

    const int T = SEQ / KTILE;
    for (int t = 0; t < T; t++) {
        const unsigned st = sKV + (unsigned)(t & 1) * KV_STAGE;
        CP_WAIT0();
        __syncthreads();

        if (t + 1 < T) {
            const unsigned sn = sKV + (unsigned)((t + 1) & 1) * KV_STAGE;
            const int k0 = (t + 1) * KTILE;
#pragma unroll
            for (int i = 0; i < 2; i++) {
                int e = tid + i * 256;
                int r = e >> 3, c8 = (e & 7) << 3;
                cp_async16(sn + 2u * (r * STH + c8), &Kb[(size_t)(k0 + r) * HD + c8]);
                cp_async16(sn + (unsigned)(KTILE * STH * 2) + 2u * (r * STH + c8),
                           &Vb[(size_t)(k0 + r) * HD + c8]);
            }
            CP_COMMIT();
        }

        // ---- S = Q K^T (fp16 m16n8k16; warp: 16 x 64) ----
        float s[8][4];
#pragma unroll
        for (int nt = 0; nt < 8; nt++)
#pragma unroll
            for (int j = 0; j < 4; j++) s[nt][j] = 0.f;

#pragma unroll
        for (int ks = 0; ks < 4; ks++) {
            unsigned af[4];
            ldsm4(af, aQ + ks * 32);
#pragma unroll
            for (int ntp = 0; ntp < 4; ntp++) {
                unsigned kf[4];
                ldsm4(kf, st + kOff + (unsigned)(ntp * 16 * STH * 2) + ks * 32);
                mma_f16(s[2 * ntp],     af, kf[0], kf[1]);
                mma_f16(s[2 * ntp + 1], af, kf[2], kf[3]);
            }
        }

        // ---- online softmax on fragments ----
        float rmax_lo = -1e30f, rmax_hi = -1e30f;
#pragma unroll
        for (int nt = 0; nt < 8; nt++) {
            rmax_lo = fmaxf(rmax_lo, fmaxf(s[nt][0], s[nt][1]));
            rmax_hi = fmaxf(rmax_hi, fmaxf(s[nt][2], s[nt][3]));
        }
        rmax_lo = fmaxf(rmax_lo, __shfl_xor_sync(0xffffffffu, rmax_lo, 1));
        rmax_lo = fmaxf(rmax_lo, __shfl_xor_sync(0xffffffffu, rmax_lo, 2));
        rmax_hi = fmaxf(rmax_hi, __shfl_xor_sync(0xffffffffu, rmax_hi, 1));
        rmax_hi = fmaxf(rmax_hi, __shfl_xor_sync(0xffffffffu, rmax_hi, 2));

        float mn_lo = fmaxf(m_lo, rmax_lo);
        float mn_hi = fmaxf(m_hi, rmax_hi);
        float alpha_lo = __expf(m_lo - mn_lo);
        float alpha_hi = __expf(m_hi - mn_hi);
        m_lo = mn_lo; m_hi = mn_hi;

        float sum_lo = 0.f, sum_hi = 0.f;
#pragma unroll
        for (int nt = 0; nt < 8; nt++) {
            s[nt][0] = __expf(s[nt][0] - m_lo);
            s[nt][1] = __expf(s[nt][1] - m_lo);
            s[nt][2] = __expf(s[nt][2] - m_hi);
            s[nt][3] = __expf(s[nt][3] - m_hi);
            sum_lo += s[nt][0] + s[nt][1];
            sum_hi += s[nt][2] + s[nt][3];
            o[nt][0] *= alpha_lo; o[nt][1] *= alpha_lo;
            o[nt][2] *= alpha_hi; o[nt][3] *= alpha_hi;
        }
        sum_lo += __shfl_xor_sync(0xffffffffu, sum_lo, 1);
        sum_lo += __shfl_xor_sync(0xffffffffu, sum_lo, 2);
        sum_hi += __shfl_xor_sync(0xffffffffu, sum_hi, 1);
        sum_hi += __shfl_xor_sync(0xffffffffu, sum_hi, 2);
        l_lo = l_lo * alpha_lo + sum_lo;
        l_hi = l_hi * alpha_hi + sum_hi;

        // ---- O += P V  (fp16; P acc == A-frag, V via ldmatrix.trans) ----
        const unsigned stV = st + (unsigned)(KTILE * STH * 2) + vOff;
#pragma unroll
        for (int ks = 0; ks < 4; ks++) {
            unsigned af[4];
            af[0] = pack_h2(s[2 * ks][0],     s[2 * ks][1]);
            af[1] = pack_h2(s[2 * ks][2],     s[2 * ks][3]);
            af[2] = pack_h2(s[2 * ks + 1][0], s[2 * ks + 1][1]);
            af[3] = pack_h2(s[2 * ks + 1][2], s[2 * ks + 1][3]);
#pragma unroll
            for (int dtp = 0; dtp < 4; dtp++) {
                unsigned vf[4];
                ldsm4t(vf, stV + (unsigned)(ks * 16 * STH * 2) + (unsigned)(dtp * 32));
                mma_f16(o[2 * dtp],     af, vf[0], vf[1]);
                mma_f16(o[2 * dtp + 1], af, vf[2], vf[3]);
            }
        }
        __syncthreads();
    }

    // ---- epilogue: normalize, tf32-round, write [B, N, H*D] ----
    float inv_lo = 1.0f / l_lo;
    float inv_hi = 1.0f / l_hi;
#pragma unroll
    for (int nt = 0; nt < 8; nt++) {
        int r = q0 + qr + lg;
        int c = h * HD + nt * 8 + (lt << 1);
        float2 v0 = make_float2(f2tff(o[nt][0] * inv_lo), f2tff(o[nt][1] * inv_lo));
        float2 v1 = make_float2(f2tff(o[nt][2] * inv_hi), f2tff(o[nt][3] * inv_hi));
        *(float2*)&Out[(size_t)(b * SEQ + r) * C_DIM + c]     = v0;
        *(float2*)&Out[(size_t)(b * SEQ + r + 8) * C_DIM + c] = v1;
    }
}

// ---------------------------------------------------------------------------
extern "C" void kernel_launch(void* const* d_in, const int* in_sizes, int n_in,
                              void* d_out, int out_size)
{
    const float* x    = (const float*)d_in[0];
    const float* Wqkv = (const float*)d_in[1];
    const float* Wout = (const float*)d_in[2];
    const float* bout = (const float*)d_in[3];
    float* out = (float*)d_out;

    float *qkv, *attn, *xtf, *wqkv, *wout;
    __half *Qh, *Kh, *Vh;
    cudaGetSymbolAddress((void**)&qkv,  g_qkv);
    cudaGetSymbolAddress((void**)&Qh,   g_Qh);
    cudaGetSymbolAddress((void**)&Kh,   g_Kh);
    cudaGetSymbolAddress((void**)&Vh,   g_Vh);
    cudaGetSymbolAddress((void**)&attn, g_attn);
    cudaGetSymbolAddress((void**)&xtf,  g_xtf);
    cudaGetSymbolAddress((void**)&wqkv, g_wqkv);
    cudaGetSymbolAddress((void**)&wout, g_wout);

    // 0) RoPE tables + tf32 pre-rounding of GEMM operands
    rope_table<<<(SEQ * 32 + 255) / 256, 256>>>();
    {
        int n4;
        n4 = M_ROWS * C_DIM / 4;
        round_tf32<<<(n4 + 255) / 256, 256>>>((const float4*)x, (float4*)xtf, n4);
        n4 = 3 * C_DIM * C_DIM / 4;
        round_tf32<<<(n4 + 255) / 256, 256>>>((const float4*)Wqkv, (float4*)wqkv, n4);
        n4 = C_DIM * C_DIM / 4;
        round_tf32<<<(n4 + 255) / 256, 256>>>((const float4*)Wout, (float4*)wout, n4);
    }

    cudaFuncSetAttribute(gemm_tf32_db,
                         cudaFuncAttributeMaxDynamicSharedMemorySize,
                         GEMM_SMEM_BYTES);

    // 1) QKV projection
    gemm_tf32_db<<<dim3(3 * C_DIM / GBN, M_ROWS / GBM), 256, GEMM_SMEM_BYTES>>>(
        xtf, wqkv, qkv, M_ROWS, 3 * C_DIM, C_DIM, nullptr);

    // 2) RoPE + transpose (fp16 Q/K/V)
    {
        int total = BATCH * HEADS * SEQ * HD;
        rope_transpose<<<(total + 255) / 256, 256>>>(qkv, Qh, Kh, Vh);
    }

    // 3) Flash attention v6 (full fp16 mma)
    cudaFuncSetAttribute(attn_f16,
                         cudaFuncAttributeMaxDynamicSharedMemorySize,
                         ATTN_SMEM_BYTES);
    attn_f16<<<dim3(SEQ / QTILE, HEADS, BATCH), 256, ATTN_SMEM_BYTES>>>(
        Qh, Kh, Vh, attn);

    // 4) Output projection
    gemm_tf32_db<<<dim3(C_DIM / GBN, M_ROWS / GBM), 256, GEMM_SMEM_BYTES>>>(
        attn, wout, out, M_ROWS, C_DIM, C_DIM, bout);
}

// round 9
// speedup vs baseline: 2.2808x; 1.3400x over previous
#include <cuda_runtime.h>
#include <cuda_fp16.h>
#include <math.h>

// Problem constants
#define C_DIM   1024
#define HEADS   16
#define HD      64
#define BATCH   2
#define SEQ     2048
#define M_ROWS  (BATCH*SEQ)        // 4096

// Scratch (device globals: no allocation allowed)
__device__ float  g_qkv[(size_t)M_ROWS * 3 * C_DIM];          // [4096, 3072] fp32
__device__ __half g_Qh[(size_t)BATCH*HEADS*SEQ*HD];           // [B,H,N,D] fp16 pre-scaled
__device__ __half g_Kh[(size_t)BATCH*HEADS*SEQ*HD];
__device__ __half g_Vh[(size_t)BATCH*HEADS*SEQ*HD];
__device__ __half g_attnh[(size_t)M_ROWS * C_DIM];            // [B,N,H*D] fp16
__device__ __half g_xh[(size_t)M_ROWS * C_DIM];               // x fp16
__device__ __half g_wqkvh[(size_t)3 * C_DIM * C_DIM];         // Wqkv fp16
__device__ __half g_wouth[(size_t)C_DIM * C_DIM];             // Wout fp16
__device__ float  g_cos[SEQ * 32];
__device__ float  g_sin[SEQ * 32];

// ---------------------------------------------------------------------------
// helpers
// ---------------------------------------------------------------------------
__device__ __forceinline__ unsigned pack_h2(float lo, float hi) {
    unsigned r;
    asm("cvt.rn.f16x2.f32 %0, %1, %2;" : "=r"(r) : "f"(hi), "f"(lo));
    return r;
}

__device__ __forceinline__ void mma_f16(float* d, const unsigned* a, unsigned b0, unsigned b1) {
    asm volatile(
        "mma.sync.aligned.m16n8k16.row.col.f32.f16.f16.f32 "
        "{%0,%1,%2,%3}, {%4,%5,%6,%7}, {%8,%9}, {%0,%1,%2,%3};\n"
        : "+f"(d[0]), "+f"(d[1]), "+f"(d[2]), "+f"(d[3])
        : "r"(a[0]), "r"(a[1]), "r"(a[2]), "r"(a[3]), "r"(b0), "r"(b1));
}

__device__ __forceinline__ void ldsm4(unsigned* r, unsigned addr) {
    asm volatile(
        "ldmatrix.sync.aligned.m8n8.x4.shared.b16 {%0,%1,%2,%3}, [%4];"
        : "=r"(r[0]), "=r"(r[1]), "=r"(r[2]), "=r"(r[3]) : "r"(addr));
}
__device__ __forceinline__ void ldsm4t(unsigned* r, unsigned addr) {
    asm volatile(
        "ldmatrix.sync.aligned.m8n8.x4.trans.shared.b16 {%0,%1,%2,%3}, [%4];"
        : "=r"(r[0]), "=r"(r[1]), "=r"(r[2]), "=r"(r[3]) : "r"(addr));
}

__device__ __forceinline__ void cp_async16(unsigned saddr, const void* gaddr) {
    asm volatile("cp.async.cg.shared.global [%0], [%1], 16;" :: "r"(saddr), "l"(gaddr));
}
#define CP_COMMIT() asm volatile("cp.async.commit_group;")
#define CP_WAIT0()  asm volatile("cp.async.wait_group 0;")

// ---------------------------------------------------------------------------
// fp32 -> fp16 conversion (operand prep)
// ---------------------------------------------------------------------------
__global__ void to_half(const float4* __restrict__ in, __half2* __restrict__ out, int n4)
{
    int i = blockIdx.x * blockDim.x + threadIdx.x;
    if (i < n4) {
        float4 v = in[i];
        out[2 * i]     = __floats2half2_rn(v.x, v.y);
        out[2 * i + 1] = __floats2half2_rn(v.z, v.w);
    }
}

// ---------------------------------------------------------------------------
// fp16 GEMM (NT), cp.async 2-stage double-buffered, ldmatrix fragments.
// C[M,N](fp32) = A[M,K](fp16) * B[N,K]^T(fp16) (+ bias)
// Block 128x128, BK=64, 256 threads (8 warps: 2m x 4n, warp tile 64x32)
// ---------------------------------------------------------------------------
#define GBM 128
#define GBN 128
#define GBK 64
#define GSH 72                                  // halves/row: 144B, conflict-free
#define GSTAGE_BYTES ((GBM + GBN) * GSH * 2)    // 36864
#define GEMM_SMEM_BYTES (2 * GSTAGE_BYTES)      // 73728

__global__ __launch_bounds__(256, 2)
void gemm_f16_db(const __half* __restrict__ A, const __half* __restrict__ B,
                 float* __restrict__ C, int M, int N, int K,
                 const float* __restrict__ bias)
{
    extern __shared__ __half gsm[];

    const int tid  = threadIdx.x;
    const int lane = tid & 31;
    const int warp = tid >> 5;
    const int wm   = (warp >> 2) * 64;
    const int wn   = (warp & 3) * 32;
    const int m0   = blockIdx.y * GBM;
    const int n0   = blockIdx.x * GBN;
    const int lg   = lane >> 2;
    const int lt   = lane & 3;
    const int t8   = lane >> 3;
    const int rr   = lane & 7;

    const unsigned sA = (unsigned)__cvta_generic_to_shared(gsm);
    const unsigned sB = sA + GBM * GSH * 2;

    // ldmatrix bases (same proven pattern as attention S-phase)
    unsigned aab[4];
#pragma unroll
    for (int mt = 0; mt < 4; mt++)
        aab[mt] = sA + 2u * ((wm + mt * 16 + (t8 & 1) * 8 + rr) * GSH + (t8 >> 1) * 8);
    unsigned bbb[2];
#pragma unroll
    for (int ntp = 0; ntp < 2; ntp++)
        bbb[ntp] = sB + 2u * ((wn + ntp * 16 + (t8 >> 1) * 8 + rr) * GSH + (t8 & 1) * 8);

    float acc[4][4][4];
#pragma unroll
    for (int mt = 0; mt < 4; mt++)
#pragma unroll
        for (int nt = 0; nt < 4; nt++)
#pragma unroll
            for (int j = 0; j < 4; j++) acc[mt][nt][j] = 0.f;

    const int T = K / GBK;

    // prefetch tile 0 (per stage: 128 rows x 64 halves per operand; 8 cp/thread)
    {
#pragma unroll
        for (int i = 0; i < 4; i++) {
            int e = tid + i * 256;
            int r = e >> 3, c8 = (e & 7) << 3;
            cp_async16(sA + 2u * (r * GSH + c8), &A[(size_t)(m0 + r) * K + c8]);
            cp_async16(sB + 2u * (r * GSH + c8), &B[(size_t)(n0 + r) * K + c8]);
        }
        CP_COMMIT();
    }

    for (int t = 0; t < T; t++) {
        const unsigned soff = (unsigned)(t & 1) * GSTAGE_BYTES;
        CP_WAIT0();
        __syncthreads();

        if (t + 1 < T) {
            const unsigned snext = (unsigned)((t + 1) & 1) * GSTAGE_BYTES;
            const int k0 = (t + 1) * GBK;
#pragma unroll
            for (int i = 0; i < 4; i++) {
                int e = tid + i * 256;
                int r = e >> 3, c8 = (e & 7) << 3;
                cp_async16(sA + snext + 2u * (r * GSH + c8),
                           &A[(size_t)(m0 + r) * K + k0 + c8]);
                cp_async16(sB + snext + 2u * (r * GSH + c8),
                           &B[(size_t)(n0 + r) * K + k0 + c8]);
            }
            CP_COMMIT();
        }

#pragma unroll
        for (int ks = 0; ks < 4; ks++) {           // 4 k16-steps = BK 64
            unsigned af[4][4], bf[2][4];
#pragma unroll
            for (int mt = 0; mt < 4; mt++) ldsm4(af[mt], aab[mt] + soff + ks * 32);
#pragma unroll
            for (int ntp = 0; ntp < 2; ntp++) ldsm4(bf[ntp], bbb[ntp] + soff + ks * 32);
#pragma unroll
            for (int mt = 0; mt < 4; mt++)
#pragma unroll
                for (int nt = 0; nt < 4; nt++)
                    mma_f16(acc[mt][nt], af[mt],
                            bf[nt >> 1][(nt & 1) * 2], bf[nt >> 1][(nt & 1) * 2 + 1]);
        }
        __syncthreads();
    }

#pragma unroll
    for (int mt = 0; mt < 4; mt++) {
#pragma unroll
        for (int nt = 0; nt < 4; nt++) {
            int r = m0 + wm + mt * 16 + lg;
            int c = n0 + wn + nt * 8 + (lt << 1);
            float b0 = bias ? bias[c] : 0.f;
            float b1 = bias ? bias[c + 1] : 0.f;
            float2 v0 = make_float2(acc[mt][nt][0] + b0, acc[mt][nt][1] + b1);
            float2 v1 = make_float2(acc[mt][nt][2] + b0, acc[mt][nt][3] + b1);
            *(float2*)&C[(size_t)r * N + c]       = v0;
            *(float2*)&C[(size_t)(r + 8) * N + c] = v1;
        }
    }
}

// ---------------------------------------------------------------------------
// RoPE cos/sin table
// ---------------------------------------------------------------------------
__global__ void rope_table()
{
    int idx = blockIdx.x * blockDim.x + threadIdx.x;
    if (idx >= SEQ * 32) return;
    int i = idx & 31;
    int n = idx >> 5;
    float inv_freq = (float)pow(10000.0, -(double)i / 32.0);
    float phase = (float)n * inv_freq;
    g_cos[idx] = (float)cos((double)phase);
    g_sin[idx] = (float)sin((double)phase);
}

// ---------------------------------------------------------------------------
// RoPE + transpose: qkv(fp32) -> Q (fp16 pre-scaled 0.125), K, V (fp16) [B,H,N,D]
// ---------------------------------------------------------------------------
__global__ void rope_transpose(const float* __restrict__ qkv,
                               __half* __restrict__ Q, __half* __restrict__ K,
                               __half* __restrict__ V)
{
    int idx = blockIdx.x * blockDim.x + threadIdx.x;
    if (idx >= BATCH * HEADS * SEQ * HD) return;
    int d = idx & (HD - 1);
    int n = (idx >> 6) & (SEQ - 1);
    int h = (idx >> 17) & (HEADS - 1);
    int b = idx >> 21;

    const size_t mrow = (size_t)(b * SEQ + n) * (3 * C_DIM);
    const int col = h * HD + d;

    float qv = qkv[mrow + col];
    float kv = qkv[mrow + C_DIM + col];
    float vv = qkv[mrow + 2 * C_DIM + col];

    int i = d & 31;
    float c = g_cos[n * 32 + i];
    float s = g_sin[n * 32 + i];

    float qp = (d < 32) ? -qkv[mrow + col + 32] : qkv[mrow + col - 32];
    float kp = (d < 32) ? -qkv[mrow + C_DIM + col + 32] : qkv[mrow + C_DIM + col - 32];

    size_t o = ((size_t)(b * HEADS + h) * SEQ + n) * HD + d;
    Q[o] = __float2half((qv * c + qp * s) * 0.125f);
    K[o] = __float2half(kv * c + kp * s);
    V[o] = __float2half(vv);
}

// ---------------------------------------------------------------------------
// Flash attention — full fp16 mma (m16n8k16), fp32 accum/softmax (R8-proven):
//  - 128 Q rows/block, 8 warps; 64-row KV tiles, cp.async double-buffered
//  - epilogue writes fp16 (out-proj consumes directly)
// ---------------------------------------------------------------------------
#define QTILE 128
#define KTILE 64
#define STH   72
#define Q_BYTES   (QTILE * STH * 2)
#define KV_STAGE  (2 * KTILE * STH * 2)
#define ATTN_SMEM_BYTES (Q_BYTES + 2 * KV_STAGE)  // 55296

__global__ __launch_bounds__(256)
void attn_f16(const __half* __restrict__ Q, const __half* __restrict__ K,
              const __half* __restrict__ V, __half* __restrict__ Out)
{
    extern __shared__ __half hsm[];

    const int tid  = threadIdx.x;
    const int lane = tid & 31;
    const int warp = tid >> 5;
    const int lg   = lane >> 2;
    const int lt   = lane & 3;
    const int t8   = lane >> 3;
    const int rr   = lane & 7;
    const int b = blockIdx.z, h = blockIdx.y;
    const int q0 = blockIdx.x * QTILE;
    const int qr = warp * 16;

    const unsigned sQ  = (unsigned)__cvta_generic_to_shared(hsm);
    const unsigned sKV = sQ + Q_BYTES;

    const __half* Qb = Q + (size_t)(b * HEADS + h) * SEQ * HD;
    const __half* Kb = K + (size_t)(b * HEADS + h) * SEQ * HD;
    const __half* Vb = V + (size_t)(b * HEADS + h) * SEQ * HD;

    const unsigned aQ = sQ + 2u * ((qr + (t8 & 1) * 8 + rr) * STH + (t8 >> 1) * 8);
    const unsigned kOff = 2u * (((t8 >> 1) * 8 + rr) * STH + (t8 & 1) * 8);
    const unsigned vOff = 2u * ((8 * (t8 & 1) + rr) * STH + 8 * (t8 >> 1));

#pragma unroll
    for (int i = 0; i < 4; i++) {
        int e = tid + i * 256;
        int r = e >> 3, c8 = (e & 7) << 3;
        *(uint4*)&hsm[r * STH + c8] = *(const uint4*)&Qb[(size_t)(q0 + r) * HD + c8];
    }

    {
        const unsigned st = sKV;
#pragma unroll
        for (int i = 0; i < 2; i++) {
            int e = tid + i * 256;
            int r = e >> 3, c8 = (e & 7) << 3;
            cp_async16(st + 2u * (r * STH + c8), &Kb[(size_t)r * HD + c8]);
            cp_async16(st + (unsigned)(KTILE * STH * 2) + 2u * (r * STH + c8),
                       &Vb[(size_t)r * HD + c8]);
        }
        CP_COMMIT();
    }

    float o[8][4];
#pragma unroll
    for (int nt = 0; nt < 8; nt++)
#pragma unroll
        for (int j = 0; j < 4; j++) o[nt][j] = 0.f;
    float m_lo = -1e30f, m_hi = -1e30f, l_lo = 0.f, l_hi = 0.f;

    const int T = SEQ / KTILE;
    for (int t = 0; t < T; t++) {
        const unsigned st = sKV + (unsigned)(t & 1) * KV_STAGE;
        CP_WAIT0();
        __syncthreads();

        if (t + 1 < T) {
            const unsigned sn = sKV + (unsigned)((t + 1) & 1) * KV_STAGE;
            const int k0 = (t + 1) * KTILE;
#pragma unroll
            for (int i = 0; i < 2; i++) {
                int e = tid + i * 256;
                int r = e >> 3, c8 = (e & 7) << 3;
                cp_async16(sn + 2u * (r * STH + c8), &Kb[(size_t)(k0 + r) * HD + c8]);
                cp_async16(sn + (unsigned)(KTILE * STH * 2) + 2u * (r * STH + c8),
                           &Vb[(size_t)(k0 + r) * HD + c8]);
            }
            CP_COMMIT();
        }

        // ---- S = Q K^T ----
        float s[8][4];
#pragma unroll
        for (int nt = 0; nt < 8; nt++)
#pragma unroll
            for (int j = 0; j < 4; j++) s[nt][j] = 0.f;

#pragma unroll
        for (int ks = 0; ks < 4; ks++) {
            unsigned af[4];
            ldsm4(af, aQ + ks * 32);
#pragma unroll
            for (int ntp = 0; ntp < 4; ntp++) {
                unsigned kf[4];
                ldsm4(kf, st + kOff + (unsigned)(ntp * 16 * STH * 2) + ks * 32);
                mma_f16(s[2 * ntp],     af, kf[0], kf[1]);
                mma_f16(s[2 * ntp + 1], af, kf[2], kf[3]);
            }
        }

        // ---- online softmax ----
        float rmax_lo = -1e30f, rmax_hi = -1e30f;
#pragma unroll
        for (int nt = 0; nt < 8; nt++) {
            rmax_lo = fmaxf(rmax_lo, fmaxf(s[nt][0], s[nt][1]));
            rmax_hi = fmaxf(rmax_hi, fmaxf(s[nt][2], s[nt][3]));
        }
        rmax_lo = fmaxf(rmax_lo, __shfl_xor_sync(0xffffffffu, rmax_lo, 1));
        rmax_lo = fmaxf(rmax_lo, __shfl_xor_sync(0xffffffffu, rmax_lo, 2));
        rmax_hi = fmaxf(rmax_hi, __shfl_xor_sync(0xffffffffu, rmax_hi, 1));
        rmax_hi = fmaxf(rmax_hi, __shfl_xor_sync(0xffffffffu, rmax_hi, 2));

        float mn_lo = fmaxf(m_lo, rmax_lo);
        float mn_hi = fmaxf(m_hi, rmax_hi);
        float alpha_lo = __expf(m_lo - mn_lo);
        float alpha_hi = __expf(m_hi - mn_hi);
        m_lo = mn_lo; m_hi = mn_hi;

        float sum_lo = 0.f, sum_hi = 0.f;
#pragma unroll
        for (int nt = 0; nt < 8; nt++) {
            s[nt][0] = __expf(s[nt][0] - m_lo);
            s[nt][1] = __expf(s[nt][1] - m_lo);
            s[nt][2] = __expf(s[nt][2] - m_hi);
            s[nt][3] = __expf(s[nt][3] - m_hi);
            sum_lo += s[nt][0] + s[nt][1];
            sum_hi += s[nt][2] + s[nt][3];
            o[nt][0] *= alpha_lo; o[nt][1] *= alpha_lo;
            o[nt][2] *= alpha_hi; o[nt][3] *= alpha_hi;
        }
        sum_lo += __shfl_xor_sync(0xffffffffu, sum_lo, 1);
        sum_lo += __shfl_xor_sync(0xffffffffu, sum_lo, 2);
        sum_hi += __shfl_xor_sync(0xffffffffu, sum_hi, 1);
        sum_hi += __shfl_xor_sync(0xffffffffu, sum_hi, 2);
        l_lo = l_lo * alpha_lo + sum_lo;
        l_hi = l_hi * alpha_hi + sum_hi;

        // ---- O += P V ----
        const unsigned stV = st + (unsigned)(KTILE * STH * 2) + vOff;
#pragma unroll
        for (int ks = 0; ks < 4; ks++) {
            unsigned af[4];
            af[0] = pack_h2(s[2 * ks][0],     s[2 * ks][1]);
            af[1] = pack_h2(s[2 * ks][2],     s[2 * ks][3]);
            af[2] = pack_h2(s[2 * ks + 1][0], s[2 * ks + 1][1]);
            af[3] = pack_h2(s[2 * ks + 1][2], s[2 * ks + 1][3]);
#pragma unroll
            for (int dtp = 0; dtp < 4; dtp++) {
                unsigned vf[4];
                ldsm4t(vf, stV + (unsigned)(ks * 16 * STH * 2) + (unsigned)(dtp * 32));
                mma_f16(o[2 * dtp],     af, vf[0], vf[1]);
                mma_f16(o[2 * dtp + 1], af, vf[2], vf[3]);
            }
        }
        __syncthreads();
    }

    // ---- epilogue: normalize, write fp16 [B, N, H*D] ----
    float inv_lo = 1.0f / l_lo;
    float inv_hi = 1.0f / l_hi;
#pragma unroll
    for (int nt = 0; nt < 8; nt++) {
        int r = q0 + qr + lg;
        int c = h * HD + nt * 8 + (lt << 1);
        __half2 v0 = __floats2half2_rn(o[nt][0] * inv_lo, o[nt][1] * inv_lo);
        __half2 v1 = __floats2half2_rn(o[nt][2] * inv_hi, o[nt][3] * inv_hi);
        *(__half2*)&Out[(size_t)(b * SEQ + r) * C_DIM + c]     = v0;
        *(__half2*)&Out[(size_t)(b * SEQ + r + 8) * C_DIM + c] = v1;
    }
}

// ---------------------------------------------------------------------------
extern "C" void kernel_launch(void* const* d_in, const int* in_sizes, int n_in,
                              void* d_out, int out_size)
{
    const float* x    = (const float*)d_in[0];
    const float* Wqkv = (const float*)d_in[1];
    const float* Wout = (const float*)d_in[2];
    const float* bout = (const float*)d_in[3];
    float* out = (float*)d_out;

    float *qkv;
    __half *Qh, *Kh, *Vh, *attnh, *xh, *wqkvh, *wouth;
    cudaGetSymbolAddress((void**)&qkv,   g_qkv);
    cudaGetSymbolAddress((void**)&Qh,    g_Qh);
    cudaGetSymbolAddress((void**)&Kh,    g_Kh);
    cudaGetSymbolAddress((void**)&Vh,    g_Vh);
    cudaGetSymbolAddress((void**)&attnh, g_attnh);
    cudaGetSymbolAddress((void**)&xh,    g_xh);
    cudaGetSymbolAddress((void**)&wqkvh, g_wqkvh);
    cudaGetSymbolAddress((void**)&wouth, g_wouth);

    // 0) RoPE tables + fp16 operand prep
    rope_table<<<(SEQ * 32 + 255) / 256, 256>>>();
    {
        int n4;
        n4 = M_ROWS * C_DIM / 4;
        to_half<<<(n4 + 255) / 256, 256>>>((const float4*)x, (__half2*)xh, n4);
        n4 = 3 * C_DIM * C_DIM / 4;
        to_half<<<(n4 + 255) / 256, 256>>>((const float4*)Wqkv, (__half2*)wqkvh, n4);
        n4 = C_DIM * C_DIM / 4;
        to_half<<<(n4 + 255) / 256, 256>>>((const float4*)Wout, (__half2*)wouth, n4);
    }

    cudaFuncSetAttribute(gemm_f16_db,
                         cudaFuncAttributeMaxDynamicSharedMemorySize,
                         GEMM_SMEM_BYTES);

    // 1) QKV projection (fp16 in, fp32 out)
    gemm_f16_db<<<dim3(3 * C_DIM / GBN, M_ROWS / GBM), 256, GEMM_SMEM_BYTES>>>(
        xh, wqkvh, qkv, M_ROWS, 3 * C_DIM, C_DIM, nullptr);

    // 2) RoPE + transpose (fp16 Q/K/V)
    {
        int total = BATCH * HEADS * SEQ * HD;
        rope_transpose<<<(total + 255) / 256, 256>>>(qkv, Qh, Kh, Vh);
    }

    // 3) Flash attention (full fp16 mma) -> fp16 [B,N,C]
    cudaFuncSetAttribute(attn_f16,
                         cudaFuncAttributeMaxDynamicSharedMemorySize,
                         ATTN_SMEM_BYTES);
    attn_f16<<<dim3(SEQ / QTILE, HEADS, BATCH), 256, ATTN_SMEM_BYTES>>>(
        Qh, Kh, Vh, attnh);

    // 4) Output projection (fp16 in, fp32 out + bias)
    gemm_f16_db<<<dim3(C_DIM / GBN, M_ROWS / GBM), 256, GEMM_SMEM_BYTES>>>(
        attnh, wouth, out, M_ROWS, C_DIM, C_DIM, bout);
}

// round 10
// speedup vs baseline: 2.2854x; 1.0020x over previous
#include <cuda_runtime.h>
#include <cuda_fp16.h>
#include <math.h>

// Problem constants
#define C_DIM   1024
#define HEADS   16
#define HD      64
#define BATCH   2
#define SEQ     2048
#define M_ROWS  (BATCH*SEQ)        // 4096

// Scratch (device globals: no allocation allowed)
__device__ float  g_qkv[(size_t)M_ROWS * 3 * C_DIM];          // [4096, 3072] fp32
__device__ __half g_Qh[(size_t)BATCH*HEADS*SEQ*HD];           // [B,H,N,D] fp16 pre-scaled
__device__ __half g_Kh[(size_t)BATCH*HEADS*SEQ*HD];
__device__ __half g_Vh[(size_t)BATCH*HEADS*SEQ*HD];
__device__ __half g_attnh[(size_t)M_ROWS * C_DIM];            // [B,N,H*D] fp16
__device__ __half g_xh[(size_t)M_ROWS * C_DIM];               // x fp16
__device__ __half g_wqkvh[(size_t)3 * C_DIM * C_DIM];         // Wqkv fp16
__device__ __half g_wouth[(size_t)C_DIM * C_DIM];             // Wout fp16
__device__ float  g_cos[SEQ * 32];
__device__ float  g_sin[SEQ * 32];

// ---------------------------------------------------------------------------
// helpers
// ---------------------------------------------------------------------------
__device__ __forceinline__ unsigned pack_h2(float lo, float hi) {
    unsigned r;
    asm("cvt.rn.f16x2.f32 %0, %1, %2;" : "=r"(r) : "f"(hi), "f"(lo));
    return r;
}

__device__ __forceinline__ void mma_f16(float* d, const unsigned* a, unsigned b0, unsigned b1) {
    asm volatile(
        "mma.sync.aligned.m16n8k16.row.col.f32.f16.f16.f32 "
        "{%0,%1,%2,%3}, {%4,%5,%6,%7}, {%8,%9}, {%0,%1,%2,%3};\n"
        : "+f"(d[0]), "+f"(d[1]), "+f"(d[2]), "+f"(d[3])
        : "r"(a[0]), "r"(a[1]), "r"(a[2]), "r"(a[3]), "r"(b0), "r"(b1));
}

__device__ __forceinline__ void ldsm4(unsigned* r, unsigned addr) {
    asm volatile(
        "ldmatrix.sync.aligned.m8n8.x4.shared.b16 {%0,%1,%2,%3}, [%4];"
        : "=r"(r[0]), "=r"(r[1]), "=r"(r[2]), "=r"(r[3]) : "r"(addr));
}
__device__ __forceinline__ void ldsm4t(unsigned* r, unsigned addr) {
    asm volatile(
        "ldmatrix.sync.aligned.m8n8.x4.trans.shared.b16 {%0,%1,%2,%3}, [%4];"
        : "=r"(r[0]), "=r"(r[1]), "=r"(r[2]), "=r"(r[3]) : "r"(addr));
}

__device__ __forceinline__ void cp_async16(unsigned saddr, const void* gaddr) {
    asm volatile("cp.async.cg.shared.global [%0], [%1], 16;" :: "r"(saddr), "l"(gaddr));
}
#define CP_COMMIT() asm volatile("cp.async.commit_group;")
#define CP_WAIT0()  asm volatile("cp.async.wait_group 0;")

// ---------------------------------------------------------------------------
// fp32 -> fp16 conversion (operand prep)
// ---------------------------------------------------------------------------
__global__ void to_half(const float4* __restrict__ in, __half2* __restrict__ out, int n4)
{
    int i = blockIdx.x * blockDim.x + threadIdx.x;
    if (i < n4) {
        float4 v = in[i];
        out[2 * i]     = __floats2half2_rn(v.x, v.y);
        out[2 * i + 1] = __floats2half2_rn(v.z, v.w);
    }
}

// ---------------------------------------------------------------------------
// fp16 GEMM (NT), cp.async 2-stage double-buffered, ldmatrix fragments.
// C[M,N](fp32) = A[M,K](fp16) * B[N,K]^T(fp16) (+ bias)
// ---------------------------------------------------------------------------
#define GBM 128
#define GBN 128
#define GBK 64
#define GSH 72
#define GSTAGE_BYTES ((GBM + GBN) * GSH * 2)    // 36864
#define GEMM_SMEM_BYTES (2 * GSTAGE_BYTES)      // 73728

__global__ __launch_bounds__(256, 2)
void gemm_f16_db(const __half* __restrict__ A, const __half* __restrict__ B,
                 float* __restrict__ C, int M, int N, int K,
                 const float* __restrict__ bias)
{
    extern __shared__ __half gsm[];

    const int tid  = threadIdx.x;
    const int lane = tid & 31;
    const int warp = tid >> 5;
    const int wm   = (warp >> 2) * 64;
    const int wn   = (warp & 3) * 32;
    const int m0   = blockIdx.y * GBM;
    const int n0   = blockIdx.x * GBN;
    const int lg   = lane >> 2;
    const int lt   = lane & 3;
    const int t8   = lane >> 3;
    const int rr   = lane & 7;

    const unsigned sA = (unsigned)__cvta_generic_to_shared(gsm);
    const unsigned sB = sA + GBM * GSH * 2;

    unsigned aab[4];
#pragma unroll
    for (int mt = 0; mt < 4; mt++)
        aab[mt] = sA + 2u * ((wm + mt * 16 + (t8 & 1) * 8 + rr) * GSH + (t8 >> 1) * 8);
    unsigned bbb[2];
#pragma unroll
    for (int ntp = 0; ntp < 2; ntp++)
        bbb[ntp] = sB + 2u * ((wn + ntp * 16 + (t8 >> 1) * 8 + rr) * GSH + (t8 & 1) * 8);

    float acc[4][4][4];
#pragma unroll
    for (int mt = 0; mt < 4; mt++)
#pragma unroll
        for (int nt = 0; nt < 4; nt++)
#pragma unroll
            for (int j = 0; j < 4; j++) acc[mt][nt][j] = 0.f;

    const int T = K / GBK;

    {
#pragma unroll
        for (int i = 0; i < 4; i++) {
            int e = tid + i * 256;
            int r = e >> 3, c8 = (e & 7) << 3;
            cp_async16(sA + 2u * (r * GSH + c8), &A[(size_t)(m0 + r) * K + c8]);
            cp_async16(sB + 2u * (r * GSH + c8), &B[(size_t)(n0 + r) * K + c8]);
        }
        CP_COMMIT();
    }

    for (int t = 0; t < T; t++) {
        const unsigned soff = (unsigned)(t & 1) * GSTAGE_BYTES;
        CP_WAIT0();
        __syncthreads();

        if (t + 1 < T) {
            const unsigned snext = (unsigned)((t + 1) & 1) * GSTAGE_BYTES;
            const int k0 = (t + 1) * GBK;
#pragma unroll
            for (int i = 0; i < 4; i++) {
                int e = tid + i * 256;
                int r = e >> 3, c8 = (e & 7) << 3;
                cp_async16(sA + snext + 2u * (r * GSH + c8),
                           &A[(size_t)(m0 + r) * K + k0 + c8]);
                cp_async16(sB + snext + 2u * (r * GSH + c8),
                           &B[(size_t)(n0 + r) * K + k0 + c8]);
            }
            CP_COMMIT();
        }

#pragma unroll
        for (int ks = 0; ks < 4; ks++) {
            unsigned af[4][4], bf[2][4];
#pragma unroll
            for (int mt = 0; mt < 4; mt++) ldsm4(af[mt], aab[mt] + soff + ks * 32);
#pragma unroll
            for (int ntp = 0; ntp < 2; ntp++) ldsm4(bf[ntp], bbb[ntp] + soff + ks * 32);
#pragma unroll
            for (int mt = 0; mt < 4; mt++)
#pragma unroll
                for (int nt = 0; nt < 4; nt++)
                    mma_f16(acc[mt][nt], af[mt],
                            bf[nt >> 1][(nt & 1) * 2], bf[nt >> 1][(nt & 1) * 2 + 1]);
        }
        __syncthreads();
    }

#pragma unroll
    for (int mt = 0; mt < 4; mt++) {
#pragma unroll
        for (int nt = 0; nt < 4; nt++) {
            int r = m0 + wm + mt * 16 + lg;
            int c = n0 + wn + nt * 8 + (lt << 1);
            float b0 = bias ? bias[c] : 0.f;
            float b1 = bias ? bias[c + 1] : 0.f;
            float2 v0 = make_float2(acc[mt][nt][0] + b0, acc[mt][nt][1] + b1);
            float2 v1 = make_float2(acc[mt][nt][2] + b0, acc[mt][nt][3] + b1);
            *(float2*)&C[(size_t)r * N + c]       = v0;
            *(float2*)&C[(size_t)(r + 8) * N + c] = v1;
        }
    }
}

// ---------------------------------------------------------------------------
// RoPE cos/sin table
// ---------------------------------------------------------------------------
__global__ void rope_table()
{
    int idx = blockIdx.x * blockDim.x + threadIdx.x;
    if (idx >= SEQ * 32) return;
    int i = idx & 31;
    int n = idx >> 5;
    float inv_freq = (float)pow(10000.0, -(double)i / 32.0);
    float phase = (float)n * inv_freq;
    g_cos[idx] = (float)cos((double)phase);
    g_sin[idx] = (float)sin((double)phase);
}

// ---------------------------------------------------------------------------
// RoPE + transpose v2 (rotation-pair symmetric, vectorized):
// thread handles (b,h,n, d=2i2, 2i2+1) AND the partners d+32 — each qkv value
// read exactly once (float2), outputs written as half2. Bit-identical math:
//   Q[d]    = (q_lo*c - q_hi*s) * 0.125
//   Q[d+32] = (q_hi*c + q_lo*s) * 0.125   (cos/sin[d+32] == cos/sin[d])
// ---------------------------------------------------------------------------
__global__ void rope_transpose(const float* __restrict__ qkv,
                               __half* __restrict__ Q, __half* __restrict__ K,
                               __half* __restrict__ V)
{
    int idx = blockIdx.x * blockDim.x + threadIdx.x;   // over B*H*N*16
    if (idx >= BATCH * HEADS * SEQ * 16) return;
    int i2 = idx & 15;                 // pair-of-2 index: d = 2*i2, 2*i2+1
    int n  = (idx >> 4) & (SEQ - 1);
    int h  = (idx >> 15) & (HEADS - 1);
    int b  = idx >> 19;

    const size_t mrow = (size_t)(b * SEQ + n) * (3 * C_DIM);
    const int col = h * HD + 2 * i2;

    float2 qlo = *(const float2*)&qkv[mrow + col];
    float2 qhi = *(const float2*)&qkv[mrow + col + 32];
    float2 klo = *(const float2*)&qkv[mrow + C_DIM + col];
    float2 khi = *(const float2*)&qkv[mrow + C_DIM + col + 32];
    float2 vlo = *(const float2*)&qkv[mrow + 2 * C_DIM + col];
    float2 vhi = *(const float2*)&qkv[mrow + 2 * C_DIM + col + 32];

    float2 cc = *(const float2*)&g_cos[n * 32 + 2 * i2];
    float2 ss = *(const float2*)&g_sin[n * 32 + 2 * i2];

    size_t o = ((size_t)(b * HEADS + h) * SEQ + n) * HD + 2 * i2;

    *(__half2*)&Q[o]      = __floats2half2_rn((qlo.x * cc.x - qhi.x * ss.x) * 0.125f,
                                              (qlo.y * cc.y - qhi.y * ss.y) * 0.125f);
    *(__half2*)&Q[o + 32] = __floats2half2_rn((qhi.x * cc.x + qlo.x * ss.x) * 0.125f,
                                              (qhi.y * cc.y + qlo.y * ss.y) * 0.125f);
    *(__half2*)&K[o]      = __floats2half2_rn(klo.x * cc.x - khi.x * ss.x,
                                              klo.y * cc.y - khi.y * ss.y);
    *(__half2*)&K[o + 32] = __floats2half2_rn(khi.x * cc.x + klo.x * ss.x,
                                              khi.y * cc.y + klo.y * ss.y);
    *(__half2*)&V[o]      = __floats2half2_rn(vlo.x, vlo.y);
    *(__half2*)&V[o + 32] = __floats2half2_rn(vhi.x, vhi.y);
}

// ---------------------------------------------------------------------------
// Flash attention — full fp16 mma, Q fragments hoisted to registers:
//  - 128 Q rows/block, 8 warps; 64-row KV tiles, cp.async double-buffered
// ---------------------------------------------------------------------------
#define QTILE 128
#define KTILE 64
#define STH   72
#define Q_BYTES   (QTILE * STH * 2)
#define KV_STAGE  (2 * KTILE * STH * 2)
#define ATTN_SMEM_BYTES (Q_BYTES + 2 * KV_STAGE)  // 55296

__global__ __launch_bounds__(256)
void attn_f16(const __half* __restrict__ Q, const __half* __restrict__ K,
              const __half* __restrict__ V, __half* __restrict__ Out)
{
    extern __shared__ __half hsm[];

    const int tid  = threadIdx.x;
    const int lane = tid & 31;
    const int warp = tid >> 5;
    const int lg   = lane >> 2;
    const int lt   = lane & 3;
    const int t8   = lane >> 3;
    const int rr   = lane & 7;
    const int b = blockIdx.z, h = blockIdx.y;
    const int q0 = blockIdx.x * QTILE;
    const int qr = warp * 16;

    const unsigned sQ  = (unsigned)__cvta_generic_to_shared(hsm);
    const unsigned sKV = sQ + Q_BYTES;

    const __half* Qb = Q + (size_t)(b * HEADS + h) * SEQ * HD;
    const __half* Kb = K + (size_t)(b * HEADS + h) * SEQ * HD;
    const __half* Vb = V + (size_t)(b * HEADS + h) * SEQ * HD;

    const unsigned aQ = sQ + 2u * ((qr + (t8 & 1) * 8 + rr) * STH + (t8 >> 1) * 8);
    const unsigned kOff = 2u * (((t8 >> 1) * 8 + rr) * STH + (t8 & 1) * 8);
    const unsigned vOff = 2u * ((8 * (t8 & 1) + rr) * STH + 8 * (t8 >> 1));

    // Q tile fill
#pragma unroll
    for (int i = 0; i < 4; i++) {
        int e = tid + i * 256;
        int r = e >> 3, c8 = (e & 7) << 3;
        *(uint4*)&hsm[r * STH + c8] = *(const uint4*)&Qb[(size_t)(q0 + r) * HD + c8];
    }

    // KV tile 0 prefetch
    {
        const unsigned st = sKV;
#pragma unroll
        for (int i = 0; i < 2; i++) {
            int e = tid + i * 256;
            int r = e >> 3, c8 = (e & 7) << 3;
            cp_async16(st + 2u * (r * STH + c8), &Kb[(size_t)r * HD + c8]);
            cp_async16(st + (unsigned)(KTILE * STH * 2) + 2u * (r * STH + c8),
                       &Vb[(size_t)r * HD + c8]);
        }
        CP_COMMIT();
    }

    // Hoist Q fragments into registers (tile-invariant)
    __syncthreads();
    unsigned aq[4][4];
#pragma unroll
    for (int ks = 0; ks < 4; ks++) ldsm4(aq[ks], aQ + ks * 32);

    float o[8][4];
#pragma unroll
    for (int nt = 0; nt < 8; nt++)
#pragma unroll
        for (int j = 0; j < 4; j++) o[nt][j] = 0.f;
    float m_lo = -1e30f, m_hi = -1e30f, l_lo = 0.f, l_hi = 0.f;

    const int T = SEQ / KTILE;
    for (int t = 0; t < T; t++) {
        const unsigned st = sKV + (unsigned)(t & 1) * KV_STAGE;
        CP_WAIT0();
        __syncthreads();

        if (t + 1 < T) {
            const unsigned sn = sKV + (unsigned)((t + 1) & 1) * KV_STAGE;
            const int k0 = (t + 1) * KTILE;
#pragma unroll
            for (int i = 0; i < 2; i++) {
                int e = tid + i * 256;
                int r = e >> 3, c8 = (e & 7) << 3;
                cp_async16(sn + 2u * (r * STH + c8), &Kb[(size_t)(k0 + r) * HD + c8]);
                cp_async16(sn + (unsigned)(KTILE * STH * 2) + 2u * (r * STH + c8),
                           &Vb[(size_t)(k0 + r) * HD + c8]);
            }
            CP_COMMIT();
        }

        // ---- S = Q K^T ----
        float s[8][4];
#pragma unroll
        for (int nt = 0; nt < 8; nt++)
#pragma unroll
            for (int j = 0; j < 4; j++) s[nt][j] = 0.f;

#pragma unroll
        for (int ks = 0; ks < 4; ks++) {
#pragma unroll
            for (int ntp = 0; ntp < 4; ntp++) {
                unsigned kf[4];
                ldsm4(kf, st + kOff + (unsigned)(ntp * 16 * STH * 2) + ks * 32);
                mma_f16(s[2 * ntp],     aq[ks], kf[0], kf[1]);
                mma_f16(s[2 * ntp + 1], aq[ks], kf[2], kf[3]);
            }
        }

        // ---- online softmax ----
        float rmax_lo = -1e30f, rmax_hi = -1e30f;
#pragma unroll
        for (int nt = 0; nt < 8; nt++) {
            rmax_lo = fmaxf(rmax_lo, fmaxf(s[nt][0], s[nt][1]));
            rmax_hi = fmaxf(rmax_hi, fmaxf(s[nt][2], s[nt][3]));
        }
        rmax_lo = fmaxf(rmax_lo, __shfl_xor_sync(0xffffffffu, rmax_lo, 1));
        rmax_lo = fmaxf(rmax_lo, __shfl_xor_sync(0xffffffffu, rmax_lo, 2));
        rmax_hi = fmaxf(rmax_hi, __shfl_xor_sync(0xffffffffu, rmax_hi, 1));
        rmax_hi = fmaxf(rmax_hi, __shfl_xor_sync(0xffffffffu, rmax_hi, 2));

        float mn_lo = fmaxf(m_lo, rmax_lo);
        float mn_hi = fmaxf(m_hi, rmax_hi);
        float alpha_lo = __expf(m_lo - mn_lo);
        float alpha_hi = __expf(m_hi - mn_hi);
        m_lo = mn_lo; m_hi = mn_hi;

        float sum_lo = 0.f, sum_hi = 0.f;
#pragma unroll
        for (int nt = 0; nt < 8; nt++) {
            s[nt][0] = __expf(s[nt][0] - m_lo);
            s[nt][1] = __expf(s[nt][1] - m_lo);
            s[nt][2] = __expf(s[nt][2] - m_hi);
            s[nt][3] = __expf(s[nt][3] - m_hi);
            sum_lo += s[nt][0] + s[nt][1];
            sum_hi += s[nt][2] + s[nt][3];
            o[nt][0] *= alpha_lo; o[nt][1] *= alpha_lo;
            o[nt][2] *= alpha_hi; o[nt][3] *= alpha_hi;
        }
        sum_lo += __shfl_xor_sync(0xffffffffu, sum_lo, 1);
        sum_lo += __shfl_xor_sync(0xffffffffu, sum_lo, 2);
        sum_hi += __shfl_xor_sync(0xffffffffu, sum_hi, 1);
        sum_hi += __shfl_xor_sync(0xffffffffu, sum_hi, 2);
        l_lo = l_lo * alpha_lo + sum_lo;
        l_hi = l_hi * alpha_hi + sum_hi;

        // ---- O += P V ----
        const unsigned stV = st + (unsigned)(KTILE * STH * 2) + vOff;
#pragma unroll
        for (int ks = 0; ks < 4; ks++) {
            unsigned af[4];
            af[0] = pack_h2(s[2 * ks][0],     s[2 * ks][1]);
            af[1] = pack_h2(s[2 * ks][2],     s[2 * ks][3]);
            af[2] = pack_h2(s[2 * ks + 1][0], s[2 * ks + 1][1]);
            af[3] = pack_h2(s[2 * ks + 1][2], s[2 * ks + 1][3]);
#pragma unroll
            for (int dtp = 0; dtp < 4; dtp++) {
                unsigned vf[4];
                ldsm4t(vf, stV + (unsigned)(ks * 16 * STH * 2) + (unsigned)(dtp * 32));
                mma_f16(o[2 * dtp],     af, vf[0], vf[1]);
                mma_f16(o[2 * dtp + 1], af, vf[2], vf[3]);
            }
        }
        __syncthreads();
    }

    // ---- epilogue: normalize, write fp16 [B, N, H*D] ----
    float inv_lo = 1.0f / l_lo;
    float inv_hi = 1.0f / l_hi;
#pragma unroll
    for (int nt = 0; nt < 8; nt++) {
        int r = q0 + qr + lg;
        int c = h * HD + nt * 8 + (lt << 1);
        __half2 v0 = __floats2half2_rn(o[nt][0] * inv_lo, o[nt][1] * inv_lo);
        __half2 v1 = __floats2half2_rn(o[nt][2] * inv_hi, o[nt][3] * inv_hi);
        *(__half2*)&Out[(size_t)(b * SEQ + r) * C_DIM + c]     = v0;
        *(__half2*)&Out[(size_t)(b * SEQ + r + 8) * C_DIM + c] = v1;
    }
}

// ---------------------------------------------------------------------------
extern "C" void kernel_launch(void* const* d_in, const int* in_sizes, int n_in,
                              void* d_out, int out_size)
{
    const float* x    = (const float*)d_in[0];
    const float* Wqkv = (const float*)d_in[1];
    const float* Wout = (const float*)d_in[2];
    const float* bout = (const float*)d_in[3];
    float* out = (float*)d_out;

    float *qkv;
    __half *Qh, *Kh, *Vh, *attnh, *xh, *wqkvh, *wouth;
    cudaGetSymbolAddress((void**)&qkv,   g_qkv);
    cudaGetSymbolAddress((void**)&Qh,    g_Qh);
    cudaGetSymbolAddress((void**)&Kh,    g_Kh);
    cudaGetSymbolAddress((void**)&Vh,    g_Vh);
    cudaGetSymbolAddress((void**)&attnh, g_attnh);
    cudaGetSymbolAddress((void**)&xh,    g_xh);
    cudaGetSymbolAddress((void**)&wqkvh, g_wqkvh);
    cudaGetSymbolAddress((void**)&wouth, g_wouth);

    // 0) RoPE tables + fp16 operand prep
    rope_table<<<(SEQ * 32 + 255) / 256, 256>>>();
    {
        int n4;
        n4 = M_ROWS * C_DIM / 4;
        to_half<<<(n4 + 255) / 256, 256>>>((const float4*)x, (__half2*)xh, n4);
        n4 = 3 * C_DIM * C_DIM / 4;
        to_half<<<(n4 + 255) / 256, 256>>>((const float4*)Wqkv, (__half2*)wqkvh, n4);
        n4 = C_DIM * C_DIM / 4;
        to_half<<<(n4 + 255) / 256, 256>>>((const float4*)Wout, (__half2*)wouth, n4);
    }

    cudaFuncSetAttribute(gemm_f16_db,
                         cudaFuncAttributeMaxDynamicSharedMemorySize,
                         GEMM_SMEM_BYTES);

    // 1) QKV projection
    gemm_f16_db<<<dim3(3 * C_DIM / GBN, M_ROWS / GBM), 256, GEMM_SMEM_BYTES>>>(
        xh, wqkvh, qkv, M_ROWS, 3 * C_DIM, C_DIM, nullptr);

    // 2) RoPE + transpose v2 (pair-symmetric, vectorized)
    {
        int total = BATCH * HEADS * SEQ * 16;
        rope_transpose<<<(total + 255) / 256, 256>>>(qkv, Qh, Kh, Vh);
    }

    // 3) Flash attention (Q-frag hoisted)
    cudaFuncSetAttribute(attn_f16,
                         cudaFuncAttributeMaxDynamicSharedMemorySize,
                         ATTN_SMEM_BYTES);
    attn_f16<<<dim3(SEQ / QTILE, HEADS, BATCH), 256, ATTN_SMEM_BYTES>>>(
        Qh, Kh, Vh, attnh);

    // 4) Output projection
    gemm_f16_db<<<dim3(C_DIM / GBN, M_ROWS / GBM), 256, GEMM_SMEM_BYTES>>>(
        attnh, wouth, out, M_ROWS, C_DIM, C_DIM, bout);
}